// round 2
// baseline (speedup 1.0000x reference)
#include <cuda_runtime.h>
#include <cstdint>

#define NMAX 50000
#define EMAX 500000
#define DIN  128   // input feature dim
#define H1   256   // conv1 output dim (2 * hidden)
#define H2   128   // conv2 output dim
#define DOUT 6

// ---------------- scratch (device globals; no allocation allowed) ----------
__device__ float g_accX[NMAX * DIN];   // aggregated X (layer-1 aggregate-first)
__device__ float g_h1  [NMAX * H1];    // relu(conv1 output)
__device__ float g_g2  [NMAX * H2];    // d_i * (h1 @ W2)  (scatter source, layer 2)
__device__ float g_acc2[NMAX * H2];    // layer-2 accumulator
__device__ int   g_deg [NMAX];
__device__ float g_dis [NMAX];         // deg^{-1/2} with self-loop

// ---------------- degree pipeline ------------------------------------------
__global__ void k_zero_deg(int n) {
    int i = blockIdx.x * blockDim.x + threadIdx.x;
    if (i < n) g_deg[i] = 0;
}

__global__ void k_count(const int* __restrict__ dst, int E) {
    int i = blockIdx.x * blockDim.x + threadIdx.x;
    if (i < E) atomicAdd(&g_deg[dst[i]], 1);
}

__global__ void k_isqrt(int n) {
    int i = blockIdx.x * blockDim.x + threadIdx.x;
    if (i < n) g_dis[i] = rsqrtf((float)(g_deg[i] + 1));  // +1 self-loop
}

// accX[i] = d_i * x[i]   (self-loop term of layer-1 aggregation)
__global__ void k_init_accX(const float* __restrict__ x, int n) {
    int i = blockIdx.x * blockDim.x + threadIdx.x;   // float4 index
    int total = n * (DIN / 4);
    if (i >= total) return;
    int row = i >> 5;                                 // DIN/4 == 32
    float s = g_dis[row];
    float4 v = ((const float4*)x)[i];
    v.x *= s; v.y *= s; v.z *= s; v.w *= s;
    ((float4*)g_accX)[i] = v;
}

// ---------------- edge scatter (warp per edge, 128 floats = 32 lanes x f4) --
// LAYER 1: g_accX[dst] += d_src * x[src]
// LAYER 2: g_acc2[dst] += g_g2[src]
template <int LAYER>
__global__ void k_scatter(const float* __restrict__ x,
                          const int* __restrict__ se,
                          const int* __restrict__ de, int E) {
    int gtid = blockIdx.x * blockDim.x + threadIdx.x;
    int w = gtid >> 5;
    int lane = threadIdx.x & 31;
    if (w >= E) return;
    int s = se[w];
    int d = de[w];
    float4 v;
    float* acc;
    if (LAYER == 1) {
        v = ((const float4*)x)[s * 32 + lane];
        float sc = g_dis[s];
        v.x *= sc; v.y *= sc; v.z *= sc; v.w *= sc;
        acc = g_accX;
    } else {
        v = ((const float4*)g_g2)[s * 32 + lane];
        acc = g_acc2;
    }
    float* p = acc + (size_t)d * 128 + lane * 4;
    atomicAdd(p + 0, v.x);
    atomicAdd(p + 1, v.y);
    atomicAdd(p + 2, v.z);
    atomicAdd(p + 3, v.w);
}

// ---------------- tiled SGEMM  (BM=128, BN=64, BK=16, 256 thr, 8x4/thr) -----
// MODE 1 (conv1): A = g_accX scaled by d_row on load; C = g_h1 = relu(v + b1)
// MODE 2 (conv2): A = g_h1; epilogue v *= d_row; store to g_g2 AND g_acc2
template <int MODE>
__global__ __launch_bounds__(256)
void k_gemm(const float* __restrict__ B, const float* __restrict__ bias,
            int M, int N, int K) {
    const int BM = 128, BN = 64, BK = 16;
    __shared__ float As[BK][BM];
    __shared__ float Bs[BK][BN];

    const float* A = (MODE == 1) ? g_accX : g_h1;

    int tid = threadIdx.x;
    int bm = blockIdx.x * BM;
    int bn = blockIdx.y * BN;
    int tx = tid & 15;    // col group (x4)
    int ty = tid >> 4;    // row group (x8)

    float acc[8][4];
#pragma unroll
    for (int i = 0; i < 8; i++)
#pragma unroll
        for (int j = 0; j < 4; j++) acc[i][j] = 0.f;

    int arow = tid >> 2;  // 0..63
    int ac4  = tid & 3;   // 0..3 (float4 column within BK)
    int bkr  = tid >> 4;  // 0..15
    int bc4  = tid & 15;  // 0..15

    for (int k0 = 0; k0 < K; k0 += BK) {
        // A tile -> smem (transposed), with optional row scaling
#pragma unroll
        for (int p = 0; p < 2; p++) {
            int r = arow + p * 64;
            int gr = bm + r;
            float4 v = make_float4(0.f, 0.f, 0.f, 0.f);
            if (gr < M) {
                v = *(const float4*)(A + (size_t)gr * K + k0 + ac4 * 4);
                if (MODE == 1) {
                    float s = g_dis[gr];
                    v.x *= s; v.y *= s; v.z *= s; v.w *= s;
                }
            }
            As[ac4 * 4 + 0][r] = v.x;
            As[ac4 * 4 + 1][r] = v.y;
            As[ac4 * 4 + 2][r] = v.z;
            As[ac4 * 4 + 3][r] = v.w;
        }
        // B tile -> smem
        {
            float4 v = *(const float4*)(B + (size_t)(k0 + bkr) * N + bn + bc4 * 4);
            *(float4*)&Bs[bkr][bc4 * 4] = v;
        }
        __syncthreads();
#pragma unroll
        for (int kk = 0; kk < BK; kk++) {
            float4 a0 = *(float4*)&As[kk][ty * 8];
            float4 a1 = *(float4*)&As[kk][ty * 8 + 4];
            float4 b  = *(float4*)&Bs[kk][tx * 4];
            float av[8] = {a0.x, a0.y, a0.z, a0.w, a1.x, a1.y, a1.z, a1.w};
            float bv[4] = {b.x, b.y, b.z, b.w};
#pragma unroll
            for (int i = 0; i < 8; i++)
#pragma unroll
                for (int j = 0; j < 4; j++) acc[i][j] += av[i] * bv[j];
        }
        __syncthreads();
    }

    // epilogue
    float4 bb = make_float4(0.f, 0.f, 0.f, 0.f);
    if (MODE == 1) bb = *(const float4*)(bias + bn + tx * 4);

#pragma unroll
    for (int i = 0; i < 8; i++) {
        int r = bm + ty * 8 + i;
        if (r >= M) break;
        float4 v;
        if (MODE == 1) {
            v.x = fmaxf(acc[i][0] + bb.x, 0.f);
            v.y = fmaxf(acc[i][1] + bb.y, 0.f);
            v.z = fmaxf(acc[i][2] + bb.z, 0.f);
            v.w = fmaxf(acc[i][3] + bb.w, 0.f);
            *(float4*)(g_h1 + (size_t)r * N + bn + tx * 4) = v;
        } else {
            float s = g_dis[r];
            v.x = acc[i][0] * s;
            v.y = acc[i][1] * s;
            v.z = acc[i][2] * s;
            v.w = acc[i][3] * s;
            *(float4*)(g_g2   + (size_t)r * N + bn + tx * 4) = v;
            *(float4*)(g_acc2 + (size_t)r * N + bn + tx * 4) = v;  // self-loop init
        }
    }
}

// ---------------- final: out = relu(d_i*acc2 + b2) @ Wfc + bfc --------------
__global__ void k_fc(const float* __restrict__ Wfc, const float* __restrict__ bfc,
                     const float* __restrict__ b2, float* __restrict__ out, int n) {
    int gtid = blockIdx.x * blockDim.x + threadIdx.x;
    int w = gtid >> 5;
    int lane = threadIdx.x & 31;
    if (w >= n) return;
    float s = g_dis[w];
    float acc[DOUT];
#pragma unroll
    for (int o = 0; o < DOUT; o++) acc[o] = 0.f;
#pragma unroll
    for (int t = 0; t < 4; t++) {
        int c = lane + t * 32;
        float h = fmaxf(s * g_acc2[(size_t)w * H2 + c] + b2[c], 0.f);
#pragma unroll
        for (int o = 0; o < DOUT; o++) acc[o] += h * __ldg(&Wfc[c * DOUT + o]);
    }
#pragma unroll
    for (int o = 0; o < DOUT; o++)
        for (int off = 16; off; off >>= 1)
            acc[o] += __shfl_xor_sync(0xffffffffu, acc[o], off);
    if (lane == 0) {
#pragma unroll
        for (int o = 0; o < DOUT; o++) out[(size_t)w * DOUT + o] = acc[o] + bfc[o];
    }
}

// ---------------- launch ----------------------------------------------------
extern "C" void kernel_launch(void* const* d_in, const int* in_sizes, int n_in,
                              void* d_out, int out_size) {
    const float* x   = (const float*)d_in[0];
    const float* W1  = (const float*)d_in[1];
    const float* b1  = (const float*)d_in[2];
    const float* W2  = (const float*)d_in[3];
    const float* b2  = (const float*)d_in[4];
    const float* Wfc = (const float*)d_in[5];
    const float* bfc = (const float*)d_in[6];
    const int*   ei  = (const int*)d_in[7];    // JAX default: int64 downcast to int32

    int n = in_sizes[0] / DIN;
    int E = in_sizes[7] / 2;
    const int* src = ei;
    const int* dst = ei + E;
    float* out = (float*)d_out;

    // degrees + inverse sqrt
    k_zero_deg<<<(n + 255) / 256, 256>>>(n);
    k_count<<<(E + 255) / 256, 256>>>(dst, E);
    k_isqrt<<<(n + 255) / 256, 256>>>(n);

    // layer 1: aggregate X first (128 cols), then GEMM
    k_init_accX<<<(n * (DIN / 4) + 255) / 256, 256>>>(x, n);
    {
        long long tthr = (long long)E * 32;
        k_scatter<1><<<(int)((tthr + 255) / 256), 256>>>(x, src, dst, E);
    }
    {
        dim3 grid((n + 127) / 128, H1 / 64);
        k_gemm<1><<<grid, 256>>>(W1, b1, n, H1, DIN);
    }

    // layer 2: transform first (256->128), then aggregate (128 cols)
    {
        dim3 grid((n + 127) / 128, H2 / 64);
        k_gemm<2><<<grid, 256>>>(W2, nullptr, n, H2, H1);
    }
    {
        long long tthr = (long long)E * 32;
        k_scatter<2><<<(int)((tthr + 255) / 256), 256>>>(nullptr, src, dst, E);
    }

    // head
    k_fc<<<(n * 32 + 255) / 256, 256>>>(Wfc, bfc, b2, out, n);
}

// round 3
// speedup vs baseline: 1.4040x; 1.4040x over previous
#include <cuda_runtime.h>
#include <cstdint>

#define NMAX 50000
#define EMAX 500000
#define DIN  128   // input feature dim
#define H1   256   // conv1 output dim (2 * hidden)
#define H2   128   // conv2 output dim
#define DOUT 6

// ---------------- scratch (device globals; no allocation allowed) ----------
__device__ float g_accX[NMAX * DIN];   // aggregated X (layer-1 aggregate-first)
__device__ float g_h1  [NMAX * H1];    // relu(conv1 output)
__device__ float g_g2  [NMAX * H2];    // d_i * (h1 @ W2)  (scatter source, layer 2)
__device__ float g_acc2[NMAX * H2];    // layer-2 accumulator
__device__ int   g_deg [NMAX];
__device__ float g_dis [NMAX];         // deg^{-1/2} with self-loop

// ---------------- degree pipeline ------------------------------------------
__global__ void k_zero_deg(int n) {
    int i = blockIdx.x * blockDim.x + threadIdx.x;
    if (i < n) g_deg[i] = 0;
}

__global__ void k_count(const int* __restrict__ dst, int E) {
    int i = blockIdx.x * blockDim.x + threadIdx.x;
    if (i < E) atomicAdd(&g_deg[dst[i]], 1);
}

__global__ void k_isqrt(int n) {
    int i = blockIdx.x * blockDim.x + threadIdx.x;
    if (i < n) g_dis[i] = rsqrtf((float)(g_deg[i] + 1));  // +1 self-loop
}

// accX[i] = d_i * x[i]   (self-loop term of layer-1 aggregation)
__global__ void k_init_accX(const float* __restrict__ x, int n) {
    int i = blockIdx.x * blockDim.x + threadIdx.x;   // float4 index
    int total = n * (DIN / 4);
    if (i >= total) return;
    int row = i >> 5;                                 // DIN/4 == 32
    float s = g_dis[row];
    float4 v = ((const float4*)x)[i];
    v.x *= s; v.y *= s; v.z *= s; v.w *= s;
    ((float4*)g_accX)[i] = v;
}

// ---------------- vectorized no-return global reduction --------------------
__device__ __forceinline__ void red_v4(float* p, float4 v) {
    asm volatile("red.global.add.v4.f32 [%0], {%1, %2, %3, %4};"
                 :: "l"(p), "f"(v.x), "f"(v.y), "f"(v.z), "f"(v.w)
                 : "memory");
}

// ---------------- edge scatter (warp per edge, 128 floats = 32 lanes x f4) --
// LAYER 1: g_accX[dst] += d_src * x[src]
// LAYER 2: g_acc2[dst] += g_g2[src]
template <int LAYER>
__global__ void k_scatter(const float* __restrict__ x,
                          const int* __restrict__ se,
                          const int* __restrict__ de, int E) {
    int gtid = blockIdx.x * blockDim.x + threadIdx.x;
    int w = gtid >> 5;
    int lane = threadIdx.x & 31;
    if (w >= E) return;
    int s = se[w];
    int d = de[w];
    float4 v;
    float* acc;
    if (LAYER == 1) {
        v = ((const float4*)x)[s * 32 + lane];
        float sc = g_dis[s];
        v.x *= sc; v.y *= sc; v.z *= sc; v.w *= sc;
        acc = g_accX;
    } else {
        v = ((const float4*)g_g2)[s * 32 + lane];
        acc = g_acc2;
    }
    red_v4(acc + (size_t)d * 128 + lane * 4, v);
}

// ---------------- tiled SGEMM  (BM=128, BN=128, BK=16, 256 thr, 8x8/thr) ----
// MODE 1 (conv1): A = g_accX scaled by d_row on load; C = g_h1 = relu(v + b1)
// MODE 2 (conv2): A = g_h1; epilogue v *= d_row; store to g_g2 AND g_acc2
template <int MODE>
__global__ __launch_bounds__(256)
void k_gemm(const float* __restrict__ B, const float* __restrict__ bias,
            int M, int N, int K) {
    const int BM = 128, BN = 128, BK = 16;
    __shared__ float As[BK][BM];
    __shared__ float Bs[BK][BN];

    const float* A = (MODE == 1) ? g_accX : g_h1;

    int tid = threadIdx.x;
    int bm = blockIdx.x * BM;
    int bn = blockIdx.y * BN;
    int tx = tid & 15;    // col group (x8)
    int ty = tid >> 4;    // row group (x8)

    float acc[8][8];
#pragma unroll
    for (int i = 0; i < 8; i++)
#pragma unroll
        for (int j = 0; j < 8; j++) acc[i][j] = 0.f;

    int arow = tid >> 2;  // 0..63
    int ac4  = tid & 3;   // 0..3 (float4 column within BK)
    int bkr  = tid >> 4;  // 0..15 (k row)
    int bc4  = tid & 15;  // 0..15 (float4 col group; loads bc4 and bc4+16)

    for (int k0 = 0; k0 < K; k0 += BK) {
        // A tile -> smem (transposed), with optional row scaling
#pragma unroll
        for (int p = 0; p < 2; p++) {
            int r = arow + p * 64;
            int gr = bm + r;
            float4 v = make_float4(0.f, 0.f, 0.f, 0.f);
            if (gr < M) {
                v = *(const float4*)(A + (size_t)gr * K + k0 + ac4 * 4);
                if (MODE == 1) {
                    float s = g_dis[gr];
                    v.x *= s; v.y *= s; v.z *= s; v.w *= s;
                }
            }
            As[ac4 * 4 + 0][r] = v.x;
            As[ac4 * 4 + 1][r] = v.y;
            As[ac4 * 4 + 2][r] = v.z;
            As[ac4 * 4 + 3][r] = v.w;
        }
        // B tile -> smem (two float4 per thread)
#pragma unroll
        for (int p = 0; p < 2; p++) {
            int c4 = bc4 + p * 16;
            float4 v = *(const float4*)(B + (size_t)(k0 + bkr) * N + bn + c4 * 4);
            *(float4*)&Bs[bkr][c4 * 4] = v;
        }
        __syncthreads();
#pragma unroll
        for (int kk = 0; kk < BK; kk++) {
            float4 a0 = *(float4*)&As[kk][ty * 8];
            float4 a1 = *(float4*)&As[kk][ty * 8 + 4];
            float4 b0 = *(float4*)&Bs[kk][tx * 8];
            float4 b1 = *(float4*)&Bs[kk][tx * 8 + 4];
            float av[8] = {a0.x, a0.y, a0.z, a0.w, a1.x, a1.y, a1.z, a1.w};
            float bv[8] = {b0.x, b0.y, b0.z, b0.w, b1.x, b1.y, b1.z, b1.w};
#pragma unroll
            for (int i = 0; i < 8; i++)
#pragma unroll
                for (int j = 0; j < 8; j++) acc[i][j] += av[i] * bv[j];
        }
        __syncthreads();
    }

    // epilogue
    float4 bb0 = make_float4(0.f, 0.f, 0.f, 0.f);
    float4 bb1 = make_float4(0.f, 0.f, 0.f, 0.f);
    if (MODE == 1) {
        bb0 = *(const float4*)(bias + bn + tx * 8);
        bb1 = *(const float4*)(bias + bn + tx * 8 + 4);
    }
    float bbv[8] = {bb0.x, bb0.y, bb0.z, bb0.w, bb1.x, bb1.y, bb1.z, bb1.w};

#pragma unroll
    for (int i = 0; i < 8; i++) {
        int r = bm + ty * 8 + i;
        if (r >= M) break;
        if (MODE == 1) {
#pragma unroll
            for (int h = 0; h < 2; h++) {
                float4 v;
                v.x = fmaxf(acc[i][h * 4 + 0] + bbv[h * 4 + 0], 0.f);
                v.y = fmaxf(acc[i][h * 4 + 1] + bbv[h * 4 + 1], 0.f);
                v.z = fmaxf(acc[i][h * 4 + 2] + bbv[h * 4 + 2], 0.f);
                v.w = fmaxf(acc[i][h * 4 + 3] + bbv[h * 4 + 3], 0.f);
                *(float4*)(g_h1 + (size_t)r * N + bn + tx * 8 + h * 4) = v;
            }
        } else {
            float s = g_dis[r];
#pragma unroll
            for (int h = 0; h < 2; h++) {
                float4 v;
                v.x = acc[i][h * 4 + 0] * s;
                v.y = acc[i][h * 4 + 1] * s;
                v.z = acc[i][h * 4 + 2] * s;
                v.w = acc[i][h * 4 + 3] * s;
                *(float4*)(g_g2   + (size_t)r * N + bn + tx * 8 + h * 4) = v;
                *(float4*)(g_acc2 + (size_t)r * N + bn + tx * 8 + h * 4) = v;  // self-loop init
            }
        }
    }
}

// ---------------- final: out = relu(d_i*acc2 + b2) @ Wfc + bfc --------------
__global__ void k_fc(const float* __restrict__ Wfc, const float* __restrict__ bfc,
                     const float* __restrict__ b2, float* __restrict__ out, int n) {
    int gtid = blockIdx.x * blockDim.x + threadIdx.x;
    int w = gtid >> 5;
    int lane = threadIdx.x & 31;
    if (w >= n) return;
    float s = g_dis[w];
    float acc[DOUT];
#pragma unroll
    for (int o = 0; o < DOUT; o++) acc[o] = 0.f;
#pragma unroll
    for (int t = 0; t < 4; t++) {
        int c = lane + t * 32;
        float h = fmaxf(s * g_acc2[(size_t)w * H2 + c] + b2[c], 0.f);
#pragma unroll
        for (int o = 0; o < DOUT; o++) acc[o] += h * __ldg(&Wfc[c * DOUT + o]);
    }
#pragma unroll
    for (int o = 0; o < DOUT; o++)
        for (int off = 16; off; off >>= 1)
            acc[o] += __shfl_xor_sync(0xffffffffu, acc[o], off);
    if (lane == 0) {
#pragma unroll
        for (int o = 0; o < DOUT; o++) out[(size_t)w * DOUT + o] = acc[o] + bfc[o];
    }
}

// ---------------- launch ----------------------------------------------------
extern "C" void kernel_launch(void* const* d_in, const int* in_sizes, int n_in,
                              void* d_out, int out_size) {
    const float* x   = (const float*)d_in[0];
    const float* W1  = (const float*)d_in[1];
    const float* b1  = (const float*)d_in[2];
    const float* W2  = (const float*)d_in[3];
    const float* b2  = (const float*)d_in[4];
    const float* Wfc = (const float*)d_in[5];
    const float* bfc = (const float*)d_in[6];
    const int*   ei  = (const int*)d_in[7];

    int n = in_sizes[0] / DIN;
    int E = in_sizes[7] / 2;
    const int* src = ei;
    const int* dst = ei + E;
    float* out = (float*)d_out;

    // degrees + inverse sqrt
    k_zero_deg<<<(n + 255) / 256, 256>>>(n);
    k_count<<<(E + 255) / 256, 256>>>(dst, E);
    k_isqrt<<<(n + 255) / 256, 256>>>(n);

    // layer 1: aggregate X first (128 cols), then GEMM
    k_init_accX<<<(n * (DIN / 4) + 255) / 256, 256>>>(x, n);
    {
        long long tthr = (long long)E * 32;
        k_scatter<1><<<(int)((tthr + 255) / 256), 256>>>(x, src, dst, E);
    }
    {
        dim3 grid((n + 127) / 128, H1 / 128);
        k_gemm<1><<<grid, 256>>>(W1, b1, n, H1, DIN);
    }

    // layer 2: transform first (256->128), then aggregate (128 cols)
    {
        dim3 grid((n + 127) / 128, H2 / 128);
        k_gemm<2><<<grid, 256>>>(W2, nullptr, n, H2, H1);
    }
    {
        long long tthr = (long long)E * 32;
        k_scatter<2><<<(int)((tthr + 255) / 256), 256>>>(nullptr, src, dst, E);
    }

    // head
    k_fc<<<(n * 32 + 255) / 256, 256>>>(Wfc, bfc, b2, out, n);
}

// round 5
// speedup vs baseline: 1.6961x; 1.2081x over previous
#include <cuda_runtime.h>
#include <cstdint>

#define NMAX 50000
#define EMAX 500000
#define DIN  128   // input feature dim
#define H1   256   // conv1 output dim (2 * hidden)
#define H2   128   // conv2 output dim
#define DOUT 6
#define SCAN_B 256

// ---------------- scratch (device globals; no allocation allowed) ----------
__device__ float g_accX[NMAX * DIN];   // aggregated X (layer-1)
__device__ float g_h1  [NMAX * H1];    // relu(conv1 output)
__device__ float g_g2  [NMAX * H2];    // d_i * (h1 @ W2)  (gather source, layer 2)
__device__ float g_acc2[NMAX * H2];    // layer-2 aggregate
__device__ int   g_deg [NMAX];
__device__ float g_dis [NMAX];         // (deg+1)^{-1/2}
__device__ int   g_off [NMAX];         // CSR row start
__device__ int   g_cur [NMAX];         // fill cursor; after fill == row end
__device__ int   g_eidx[EMAX];         // CSR column (src) indices
__device__ int   g_bsum[512];          // block sums for scan

// ---------------- degree pipeline ------------------------------------------
__global__ void k_zero_deg(int n) {
    int i = blockIdx.x * blockDim.x + threadIdx.x;
    if (i < n) g_deg[i] = 0;
}

__global__ void k_count(const int* __restrict__ dst, int E) {
    int i = blockIdx.x * blockDim.x + threadIdx.x;
    if (i < E) atomicAdd(&g_deg[dst[i]], 1);
}

__global__ void k_isqrt(int n) {
    int i = blockIdx.x * blockDim.x + threadIdx.x;
    if (i < n) g_dis[i] = rsqrtf((float)(g_deg[i] + 1));  // +1 self-loop
}

// ---------------- exclusive scan over g_deg -> g_off (3 kernels) ------------
__global__ void k_scan1(int n) {  // per-block scan + block sum
    __shared__ int sm[SCAN_B];
    int i = blockIdx.x * SCAN_B + threadIdx.x;
    int v = (i < n) ? g_deg[i] : 0;
    sm[threadIdx.x] = v;
    __syncthreads();
    int x = v;
#pragma unroll
    for (int off = 1; off < SCAN_B; off <<= 1) {
        int y = (threadIdx.x >= off) ? sm[threadIdx.x - off] : 0;
        __syncthreads();
        x += y;
        sm[threadIdx.x] = x;
        __syncthreads();
    }
    if (i < n) g_off[i] = x - v;                 // exclusive (block-local)
    if (threadIdx.x == SCAN_B - 1) g_bsum[blockIdx.x] = x;
}

__global__ void k_scan2(int nb) {  // single block: exclusive scan of block sums
    __shared__ int sm[512];
    int t = threadIdx.x;
    int v = (t < nb) ? g_bsum[t] : 0;
    sm[t] = v;
    __syncthreads();
    int x = v;
#pragma unroll
    for (int off = 1; off < 512; off <<= 1) {
        int y = (t >= off) ? sm[t - off] : 0;
        __syncthreads();
        x += y;
        sm[t] = x;
        __syncthreads();
    }
    if (t < nb) g_bsum[t] = x - v;               // exclusive
}

__global__ void k_scan3(int n) {  // add block base; init cursor
    int i = blockIdx.x * SCAN_B + threadIdx.x;
    if (i < n) {
        int o = g_off[i] + g_bsum[blockIdx.x];
        g_off[i] = o;
        g_cur[i] = o;
    }
}

__global__ void k_fill(const int* __restrict__ src, const int* __restrict__ dst, int E) {
    int i = blockIdx.x * blockDim.x + threadIdx.x;
    if (i < E) {
        int pos = atomicAdd(&g_cur[dst[i]], 1);
        g_eidx[pos] = src[i];
    }
}

// ---------------- CSR gather aggregation (warp per node) --------------------
// LAYER 1: g_accX[v] = d_v*x[v] + sum_{s->v} d_s*x[s]     (feat = x argument)
// LAYER 2: g_acc2[v] = g2[v]    + sum_{s->v} g2[s]        (feat = g_g2 global)
template <int LAYER>
__global__ void k_gather(const float* __restrict__ xin, int n) {
    int gtid = blockIdx.x * blockDim.x + threadIdx.x;
    int w = gtid >> 5;
    int lane = threadIdx.x & 31;
    if (w >= n) return;

    const float* feat = (LAYER == 1) ? xin : g_g2;   // device-side symbol ref
    float*       out  = (LAYER == 1) ? g_accX : g_acc2;

    float4 acc = ((const float4*)feat)[(size_t)w * 32 + lane];
    if (LAYER == 1) {
        float s = g_dis[w];
        acc.x *= s; acc.y *= s; acc.z *= s; acc.w *= s;
    }

    int beg = g_off[w];
    int end = g_cur[w];   // after fill, cursor == row end
    for (int j = beg; j < end; j += 32) {
        int cnt = min(32, end - j);
        int myidx = (lane < cnt) ? g_eidx[j + lane] : 0;
        for (int t = 0; t < cnt; t++) {
            int s = __shfl_sync(0xffffffffu, myidx, t);
            float4 v = ((const float4*)feat)[(size_t)s * 32 + lane];
            if (LAYER == 1) {
                float sc = g_dis[s];
                acc.x += v.x * sc; acc.y += v.y * sc;
                acc.z += v.z * sc; acc.w += v.w * sc;
            } else {
                acc.x += v.x; acc.y += v.y; acc.z += v.z; acc.w += v.w;
            }
        }
    }
    ((float4*)out)[(size_t)w * 32 + lane] = acc;
}

// ---------------- tiled SGEMM  (BM=128, BN=128, BK=16, 256 thr, 8x8/thr) ----
// MODE 1 (conv1): A = g_accX scaled by d_row on load; C = g_h1 = relu(v + b1)
// MODE 2 (conv2): A = g_h1; epilogue v *= d_row; store to g_g2
template <int MODE>
__global__ __launch_bounds__(256)
void k_gemm(const float* __restrict__ B, const float* __restrict__ bias,
            int M, int N, int K) {
    const int BM = 128, BN = 128, BK = 16;
    __shared__ float As[BK][BM];
    __shared__ float Bs[BK][BN];

    const float* A = (MODE == 1) ? g_accX : g_h1;

    int tid = threadIdx.x;
    int bm = blockIdx.x * BM;
    int bn = blockIdx.y * BN;
    int tx = tid & 15;    // col group (x8)
    int ty = tid >> 4;    // row group (x8)

    float acc[8][8];
#pragma unroll
    for (int i = 0; i < 8; i++)
#pragma unroll
        for (int j = 0; j < 8; j++) acc[i][j] = 0.f;

    int arow = tid >> 2;  // 0..63
    int ac4  = tid & 3;   // 0..3
    int bkr  = tid >> 4;  // 0..15
    int bc4  = tid & 15;  // 0..15

    for (int k0 = 0; k0 < K; k0 += BK) {
#pragma unroll
        for (int p = 0; p < 2; p++) {
            int r = arow + p * 64;
            int gr = bm + r;
            float4 v = make_float4(0.f, 0.f, 0.f, 0.f);
            if (gr < M) {
                v = *(const float4*)(A + (size_t)gr * K + k0 + ac4 * 4);
                if (MODE == 1) {
                    float s = g_dis[gr];
                    v.x *= s; v.y *= s; v.z *= s; v.w *= s;
                }
            }
            As[ac4 * 4 + 0][r] = v.x;
            As[ac4 * 4 + 1][r] = v.y;
            As[ac4 * 4 + 2][r] = v.z;
            As[ac4 * 4 + 3][r] = v.w;
        }
#pragma unroll
        for (int p = 0; p < 2; p++) {
            int c4 = bc4 + p * 16;
            float4 v = *(const float4*)(B + (size_t)(k0 + bkr) * N + bn + c4 * 4);
            *(float4*)&Bs[bkr][c4 * 4] = v;
        }
        __syncthreads();
#pragma unroll
        for (int kk = 0; kk < BK; kk++) {
            float4 a0 = *(float4*)&As[kk][ty * 8];
            float4 a1 = *(float4*)&As[kk][ty * 8 + 4];
            float4 b0 = *(float4*)&Bs[kk][tx * 8];
            float4 b1 = *(float4*)&Bs[kk][tx * 8 + 4];
            float av[8] = {a0.x, a0.y, a0.z, a0.w, a1.x, a1.y, a1.z, a1.w};
            float bv[8] = {b0.x, b0.y, b0.z, b0.w, b1.x, b1.y, b1.z, b1.w};
#pragma unroll
            for (int i = 0; i < 8; i++)
#pragma unroll
                for (int j = 0; j < 8; j++) acc[i][j] += av[i] * bv[j];
        }
        __syncthreads();
    }

    float4 bb0 = make_float4(0.f, 0.f, 0.f, 0.f);
    float4 bb1 = make_float4(0.f, 0.f, 0.f, 0.f);
    if (MODE == 1) {
        bb0 = *(const float4*)(bias + bn + tx * 8);
        bb1 = *(const float4*)(bias + bn + tx * 8 + 4);
    }
    float bbv[8] = {bb0.x, bb0.y, bb0.z, bb0.w, bb1.x, bb1.y, bb1.z, bb1.w};

#pragma unroll
    for (int i = 0; i < 8; i++) {
        int r = bm + ty * 8 + i;
        if (r >= M) break;
        if (MODE == 1) {
#pragma unroll
            for (int h = 0; h < 2; h++) {
                float4 v;
                v.x = fmaxf(acc[i][h * 4 + 0] + bbv[h * 4 + 0], 0.f);
                v.y = fmaxf(acc[i][h * 4 + 1] + bbv[h * 4 + 1], 0.f);
                v.z = fmaxf(acc[i][h * 4 + 2] + bbv[h * 4 + 2], 0.f);
                v.w = fmaxf(acc[i][h * 4 + 3] + bbv[h * 4 + 3], 0.f);
                *(float4*)(g_h1 + (size_t)r * N + bn + tx * 8 + h * 4) = v;
            }
        } else {
            float s = g_dis[r];
#pragma unroll
            for (int h = 0; h < 2; h++) {
                float4 v;
                v.x = acc[i][h * 4 + 0] * s;
                v.y = acc[i][h * 4 + 1] * s;
                v.z = acc[i][h * 4 + 2] * s;
                v.w = acc[i][h * 4 + 3] * s;
                *(float4*)(g_g2 + (size_t)r * N + bn + tx * 8 + h * 4) = v;
            }
        }
    }
}

// ---------------- final: out = relu(d_i*acc2 + b2) @ Wfc + bfc --------------
__global__ void k_fc(const float* __restrict__ Wfc, const float* __restrict__ bfc,
                     const float* __restrict__ b2, float* __restrict__ out, int n) {
    int gtid = blockIdx.x * blockDim.x + threadIdx.x;
    int w = gtid >> 5;
    int lane = threadIdx.x & 31;
    if (w >= n) return;
    float s = g_dis[w];
    float acc[DOUT];
#pragma unroll
    for (int o = 0; o < DOUT; o++) acc[o] = 0.f;
#pragma unroll
    for (int t = 0; t < 4; t++) {
        int c = lane + t * 32;
        float h = fmaxf(s * g_acc2[(size_t)w * H2 + c] + b2[c], 0.f);
#pragma unroll
        for (int o = 0; o < DOUT; o++) acc[o] += h * __ldg(&Wfc[c * DOUT + o]);
    }
#pragma unroll
    for (int o = 0; o < DOUT; o++)
        for (int off = 16; off; off >>= 1)
            acc[o] += __shfl_xor_sync(0xffffffffu, acc[o], off);
    if (lane == 0) {
#pragma unroll
        for (int o = 0; o < DOUT; o++) out[(size_t)w * DOUT + o] = acc[o] + bfc[o];
    }
}

// ---------------- launch ----------------------------------------------------
extern "C" void kernel_launch(void* const* d_in, const int* in_sizes, int n_in,
                              void* d_out, int out_size) {
    const float* x   = (const float*)d_in[0];
    const float* W1  = (const float*)d_in[1];
    const float* b1  = (const float*)d_in[2];
    const float* W2  = (const float*)d_in[3];
    const float* b2  = (const float*)d_in[4];
    const float* Wfc = (const float*)d_in[5];
    const float* bfc = (const float*)d_in[6];
    const int*   ei  = (const int*)d_in[7];

    int n = in_sizes[0] / DIN;
    int E = in_sizes[7] / 2;
    const int* src = ei;
    const int* dst = ei + E;
    float* out = (float*)d_out;
    int nb = (n + SCAN_B - 1) / SCAN_B;

    // degrees + inverse sqrt
    k_zero_deg<<<nb, SCAN_B>>>(n);
    k_count<<<(E + 255) / 256, 256>>>(dst, E);
    k_isqrt<<<nb, SCAN_B>>>(n);

    // CSR build (by dst)
    k_scan1<<<nb, SCAN_B>>>(n);
    k_scan2<<<1, 512>>>(nb);
    k_scan3<<<nb, SCAN_B>>>(n);
    k_fill<<<(E + 255) / 256, 256>>>(src, dst, E);

    // layer 1: gather-aggregate X (128 cols), then GEMM
    k_gather<1><<<(n * 32 + 255) / 256, 256>>>(x, n);
    {
        dim3 grid((n + 127) / 128, H1 / 128);
        k_gemm<1><<<grid, 256>>>(W1, b1, n, H1, DIN);
    }

    // layer 2: transform first (256->128), then gather-aggregate (128 cols)
    {
        dim3 grid((n + 127) / 128, H2 / 128);
        k_gemm<2><<<grid, 256>>>(W2, nullptr, n, H2, H1);
    }
    k_gather<2><<<(n * 32 + 255) / 256, 256>>>(nullptr, n);

    // head
    k_fc<<<(n * 32 + 255) / 256, 256>>>(Wfc, bfc, b2, out, n);
}

// round 6
// speedup vs baseline: 2.5595x; 1.5091x over previous
#include <cuda_runtime.h>
#include <cstdint>

#define NMAX 50000
#define EMAX 500000
#define DIN  128   // input feature dim
#define H1   256   // conv1 output dim (2 * hidden)
#define H2   128   // conv2 output dim
#define DOUT 6
#define SCAN_B 256

// ---------------- scratch (device globals; no allocation allowed) ----------
__device__ float g_accX[NMAX * DIN];   // d_v * (self + neighbor agg of d_s*x_s)
__device__ float g_h1  [NMAX * H1];    // relu(conv1 output)
__device__ float g_g2  [NMAX * H2];    // d_i * (h1 @ W2)
__device__ int   g_deg [NMAX];
__device__ float g_dis [NMAX];         // (deg+1)^{-1/2}
__device__ int   g_off [NMAX];         // CSR row start
__device__ int   g_cur [NMAX];         // fill cursor; after fill == row end
__device__ int   g_eidx[EMAX];         // CSR column (src) indices
__device__ int   g_bsum[512];          // block sums for scan

// ---------------- degree pipeline ------------------------------------------
__global__ void k_zero_deg(int n) {
    int i = blockIdx.x * blockDim.x + threadIdx.x;
    if (i < n) g_deg[i] = 0;
}

__global__ void k_count(const int* __restrict__ dst, int E) {
    int i = blockIdx.x * blockDim.x + threadIdx.x;
    if (i < E) atomicAdd(&g_deg[dst[i]], 1);
}

__global__ void k_isqrt(int n) {
    int i = blockIdx.x * blockDim.x + threadIdx.x;
    if (i < n) g_dis[i] = rsqrtf((float)(g_deg[i] + 1));  // +1 self-loop
}

// ---------------- exclusive scan over g_deg -> g_off ------------------------
__global__ void k_scan1(int n) {
    __shared__ int sm[SCAN_B];
    int i = blockIdx.x * SCAN_B + threadIdx.x;
    int v = (i < n) ? g_deg[i] : 0;
    sm[threadIdx.x] = v;
    __syncthreads();
    int x = v;
#pragma unroll
    for (int off = 1; off < SCAN_B; off <<= 1) {
        int y = (threadIdx.x >= off) ? sm[threadIdx.x - off] : 0;
        __syncthreads();
        x += y;
        sm[threadIdx.x] = x;
        __syncthreads();
    }
    if (i < n) g_off[i] = x - v;
    if (threadIdx.x == SCAN_B - 1) g_bsum[blockIdx.x] = x;
}

__global__ void k_scan2(int nb) {
    __shared__ int sm[512];
    int t = threadIdx.x;
    int v = (t < nb) ? g_bsum[t] : 0;
    sm[t] = v;
    __syncthreads();
    int x = v;
#pragma unroll
    for (int off = 1; off < 512; off <<= 1) {
        int y = (t >= off) ? sm[t - off] : 0;
        __syncthreads();
        x += y;
        sm[t] = x;
        __syncthreads();
    }
    if (t < nb) g_bsum[t] = x - v;
}

__global__ void k_scan3(int n) {
    int i = blockIdx.x * SCAN_B + threadIdx.x;
    if (i < n) {
        int o = g_off[i] + g_bsum[blockIdx.x];
        g_off[i] = o;
        g_cur[i] = o;
    }
}

__global__ void k_fill(const int* __restrict__ src, const int* __restrict__ dst, int E) {
    int i = blockIdx.x * blockDim.x + threadIdx.x;
    if (i < E) {
        int pos = atomicAdd(&g_cur[dst[i]], 1);
        g_eidx[pos] = src[i];
    }
}

// ---------------- layer-1 gather:  g_accX[v] = d_v*(d_v*x_v + sum d_s*x_s) --
__global__ void k_gather1(const float* __restrict__ x, int n) {
    int gtid = blockIdx.x * blockDim.x + threadIdx.x;
    int w = gtid >> 5;
    int lane = threadIdx.x & 31;
    if (w >= n) return;

    float s = g_dis[w];
    float4 acc = ((const float4*)x)[(size_t)w * 32 + lane];
    acc.x *= s; acc.y *= s; acc.z *= s; acc.w *= s;

    int beg = g_off[w];
    int end = g_cur[w];
    for (int j = beg; j < end; j += 32) {
        int cnt = min(32, end - j);
        int myidx = (lane < cnt) ? g_eidx[j + lane] : 0;
        for (int t = 0; t < cnt; t++) {
            int sidx = __shfl_sync(0xffffffffu, myidx, t);
            float4 v = ((const float4*)x)[(size_t)sidx * 32 + lane];
            float sc = g_dis[sidx];
            acc.x += v.x * sc; acc.y += v.y * sc;
            acc.z += v.z * sc; acc.w += v.w * sc;
        }
    }
    acc.x *= s; acc.y *= s; acc.z *= s; acc.w *= s;
    ((float4*)g_accX)[(size_t)w * 32 + lane] = acc;
}

// ---------------- tf32 helpers ----------------------------------------------
__device__ __forceinline__ uint32_t f2tf(float x) {
    uint32_t r;
    asm("cvt.rna.tf32.f32 %0, %1;" : "=r"(r) : "f"(x));
    return r;
}

__device__ __forceinline__ void mma_tf32(float& c0, float& c1, float& c2, float& c3,
                                         uint32_t a0, uint32_t a1, uint32_t a2, uint32_t a3,
                                         uint32_t b0, uint32_t b1) {
    asm volatile(
        "mma.sync.aligned.m16n8k8.row.col.f32.tf32.tf32.f32 "
        "{%0,%1,%2,%3},{%4,%5,%6,%7},{%8,%9},{%0,%1,%2,%3};"
        : "+f"(c0), "+f"(c1), "+f"(c2), "+f"(c3)
        : "r"(a0), "r"(a1), "r"(a2), "r"(a3), "r"(b0), "r"(b1));
}

// ---------------- tf32 tensor-core GEMM ------------------------------------
// Block 128x128, BK=32, 256 thr = 8 warps (2 x 4), warp tile 64x32.
// MODE 1 (conv1): A = g_accX; C = relu(v + b1) -> g_h1
// MODE 2 (conv2): A = g_h1;   C = d_row * v    -> g_g2
#define GPA 137   // As row stride (floats), As[k][m]
#define GPB 136   // Bs row stride (floats), Bs[k][n]

template <int MODE>
__global__ __launch_bounds__(256, 2)
void k_gemm_tc(const float* __restrict__ Bw, const float* __restrict__ bias,
               int M, int N, int K) {
    __shared__ uint32_t As[32 * GPA];
    __shared__ uint32_t Bs[32 * GPB];

    const float* A = (MODE == 1) ? g_accX : g_h1;

    int tid  = threadIdx.x;
    int lane = tid & 31;
    int wid  = tid >> 5;
    int warp_m = wid & 1;   // 0..1 (64 rows each)
    int warp_n = wid >> 1;  // 0..3 (32 cols each)
    int bm = blockIdx.x * 128;
    int bn = blockIdx.y * 128;

    float c[4][4][4];
#pragma unroll
    for (int mt = 0; mt < 4; mt++)
#pragma unroll
        for (int nt = 0; nt < 4; nt++)
#pragma unroll
            for (int r = 0; r < 4; r++) c[mt][nt][r] = 0.f;

    int lq = lane & 3;      // threadID in quad
    int lg = lane >> 2;     // group id

    for (int k0 = 0; k0 < K; k0 += 32) {
        // --- A tile: 128 x 32 floats = 1024 float4 loads ---
#pragma unroll
        for (int q = 0; q < 4; q++) {
            int idx = q * 256 + tid;
            int m = idx >> 3;          // 0..127
            int k4 = idx & 7;          // 0..7
            float4 v = make_float4(0.f, 0.f, 0.f, 0.f);
            if (bm + m < M)
                v = *(const float4*)(A + (size_t)(bm + m) * K + k0 + k4 * 4);
            As[(k4 * 4 + 0) * GPA + m] = f2tf(v.x);
            As[(k4 * 4 + 1) * GPA + m] = f2tf(v.y);
            As[(k4 * 4 + 2) * GPA + m] = f2tf(v.z);
            As[(k4 * 4 + 3) * GPA + m] = f2tf(v.w);
        }
        // --- B tile: 32 x 128 floats = 1024 float4 loads ---
#pragma unroll
        for (int q = 0; q < 4; q++) {
            int idx = q * 256 + tid;
            int k = idx >> 5;          // 0..31
            int n4 = idx & 31;         // 0..31
            float4 v = *(const float4*)(Bw + (size_t)(k0 + k) * N + bn + n4 * 4);
            uint32_t* p = &Bs[k * GPB + n4 * 4];
            p[0] = f2tf(v.x); p[1] = f2tf(v.y); p[2] = f2tf(v.z); p[3] = f2tf(v.w);
        }
        __syncthreads();

#pragma unroll
        for (int kk = 0; kk < 4; kk++) {
            int kb = kk * 8 + lq;
            uint32_t a[4][4];
#pragma unroll
            for (int mt = 0; mt < 4; mt++) {
                int mr = warp_m * 64 + mt * 16 + lg;
                a[mt][0] = As[kb * GPA + mr];
                a[mt][1] = As[kb * GPA + mr + 8];
                a[mt][2] = As[(kb + 4) * GPA + mr];
                a[mt][3] = As[(kb + 4) * GPA + mr + 8];
            }
            uint32_t b[4][2];
#pragma unroll
            for (int nt = 0; nt < 4; nt++) {
                int nc = warp_n * 32 + nt * 8 + lg;
                b[nt][0] = Bs[kb * GPB + nc];
                b[nt][1] = Bs[(kb + 4) * GPB + nc];
            }
#pragma unroll
            for (int mt = 0; mt < 4; mt++)
#pragma unroll
                for (int nt = 0; nt < 4; nt++)
                    mma_tf32(c[mt][nt][0], c[mt][nt][1], c[mt][nt][2], c[mt][nt][3],
                             a[mt][0], a[mt][1], a[mt][2], a[mt][3],
                             b[nt][0], b[nt][1]);
        }
        __syncthreads();
    }

    // ---- epilogue ----
#pragma unroll
    for (int mt = 0; mt < 4; mt++) {
        int row0 = bm + warp_m * 64 + mt * 16 + lg;
        int row1 = row0 + 8;
#pragma unroll
        for (int nt = 0; nt < 4; nt++) {
            int col = bn + warp_n * 32 + nt * 8 + lq * 2;
            if (MODE == 1) {
                float2 bb = *(const float2*)(bias + col);
                if (row0 < M) {
                    float2 v;
                    v.x = fmaxf(c[mt][nt][0] + bb.x, 0.f);
                    v.y = fmaxf(c[mt][nt][1] + bb.y, 0.f);
                    *(float2*)(g_h1 + (size_t)row0 * N + col) = v;
                }
                if (row1 < M) {
                    float2 v;
                    v.x = fmaxf(c[mt][nt][2] + bb.x, 0.f);
                    v.y = fmaxf(c[mt][nt][3] + bb.y, 0.f);
                    *(float2*)(g_h1 + (size_t)row1 * N + col) = v;
                }
            } else {
                if (row0 < M) {
                    float s0 = g_dis[row0];
                    float2 v = make_float2(c[mt][nt][0] * s0, c[mt][nt][1] * s0);
                    *(float2*)(g_g2 + (size_t)row0 * N + col) = v;
                }
                if (row1 < M) {
                    float s1 = g_dis[row1];
                    float2 v = make_float2(c[mt][nt][2] * s1, c[mt][nt][3] * s1);
                    *(float2*)(g_g2 + (size_t)row1 * N + col) = v;
                }
            }
        }
    }
}

// ---------------- fused layer-2 gather + FC head ----------------------------
// acc = g2[v] + sum g2[s];  h = relu(d_v*acc + b2);  out = h @ Wfc + bfc
__global__ void k_gather2fc(const float* __restrict__ Wfc, const float* __restrict__ bfc,
                            const float* __restrict__ b2, float* __restrict__ out, int n) {
    int gtid = blockIdx.x * blockDim.x + threadIdx.x;
    int w = gtid >> 5;
    int lane = threadIdx.x & 31;
    if (w >= n) return;

    float4 acc = ((const float4*)g_g2)[(size_t)w * 32 + lane];

    int beg = g_off[w];
    int end = g_cur[w];
    for (int j = beg; j < end; j += 32) {
        int cnt = min(32, end - j);
        int myidx = (lane < cnt) ? g_eidx[j + lane] : 0;
        for (int t = 0; t < cnt; t++) {
            int sidx = __shfl_sync(0xffffffffu, myidx, t);
            float4 v = ((const float4*)g_g2)[(size_t)sidx * 32 + lane];
            acc.x += v.x; acc.y += v.y; acc.z += v.z; acc.w += v.w;
        }
    }

    float s = g_dis[w];
    float4 bb = ((const float4*)b2)[lane];
    float h[4];
    h[0] = fmaxf(acc.x * s + bb.x, 0.f);
    h[1] = fmaxf(acc.y * s + bb.y, 0.f);
    h[2] = fmaxf(acc.z * s + bb.z, 0.f);
    h[3] = fmaxf(acc.w * s + bb.w, 0.f);

    int c0 = lane * 4;
    float a6[DOUT];
#pragma unroll
    for (int o = 0; o < DOUT; o++) a6[o] = 0.f;
#pragma unroll
    for (int j = 0; j < 4; j++)
#pragma unroll
        for (int o = 0; o < DOUT; o++)
            a6[o] += h[j] * __ldg(&Wfc[(c0 + j) * DOUT + o]);
#pragma unroll
    for (int o = 0; o < DOUT; o++)
        for (int off = 16; off; off >>= 1)
            a6[o] += __shfl_xor_sync(0xffffffffu, a6[o], off);
    if (lane == 0) {
#pragma unroll
        for (int o = 0; o < DOUT; o++) out[(size_t)w * DOUT + o] = a6[o] + bfc[o];
    }
}

// ---------------- launch ----------------------------------------------------
extern "C" void kernel_launch(void* const* d_in, const int* in_sizes, int n_in,
                              void* d_out, int out_size) {
    const float* x   = (const float*)d_in[0];
    const float* W1  = (const float*)d_in[1];
    const float* b1  = (const float*)d_in[2];
    const float* W2  = (const float*)d_in[3];
    const float* b2  = (const float*)d_in[4];
    const float* Wfc = (const float*)d_in[5];
    const float* bfc = (const float*)d_in[6];
    const int*   ei  = (const int*)d_in[7];

    int n = in_sizes[0] / DIN;
    int E = in_sizes[7] / 2;
    const int* src = ei;
    const int* dst = ei + E;
    float* out = (float*)d_out;
    int nb = (n + SCAN_B - 1) / SCAN_B;

    // degrees + inverse sqrt
    k_zero_deg<<<nb, SCAN_B>>>(n);
    k_count<<<(E + 255) / 256, 256>>>(dst, E);
    k_isqrt<<<nb, SCAN_B>>>(n);

    // CSR build (by dst)
    k_scan1<<<nb, SCAN_B>>>(n);
    k_scan2<<<1, 512>>>(nb);
    k_scan3<<<nb, SCAN_B>>>(n);
    k_fill<<<(E + 255) / 256, 256>>>(src, dst, E);

    // layer 1: gather-aggregate X, then tensor-core GEMM (128 -> 256) + relu
    k_gather1<<<(n * 32 + 255) / 256, 256>>>(x, n);
    {
        dim3 grid((n + 127) / 128, H1 / 128);
        k_gemm_tc<1><<<grid, 256>>>(W1, b1, n, H1, DIN);
    }

    // layer 2: GEMM (256 -> 128) with d_row epilogue, then fused gather + FC
    {
        dim3 grid((n + 127) / 128, H2 / 128);
        k_gemm_tc<2><<<grid, 256>>>(W2, nullptr, n, H2, H1);
    }
    k_gather2fc<<<(n * 32 + 255) / 256, 256>>>(Wfc, bfc, b2, out, n);
}

// round 7
// speedup vs baseline: 2.7729x; 1.0834x over previous
#include <cuda_runtime.h>
#include <cstdint>

#define NMAX 50000
#define EMAX 500000
#define DIN  128   // input feature dim
#define H1   256   // conv1 output dim (2 * hidden)
#define H2   128   // conv2 output dim
#define DOUT 6
#define SCAN_B 256

// ---------------- scratch (device globals; no allocation allowed) ----------
__device__ float g_accX[NMAX * DIN];   // d_v * (d_v*x_v + sum d_s*x_s)
__device__ float g_h1  [NMAX * H1];    // relu(conv1 output)
__device__ float g_g2  [NMAX * H2];    // d_i * (h1 @ W2)
__device__ int   g_deg [NMAX];
__device__ float g_dis [NMAX];         // (deg+1)^{-1/2}
__device__ int   g_off [NMAX];         // CSR row start
__device__ int   g_cur [NMAX];         // fill cursor; after fill == row end
__device__ int   g_eidx[EMAX];         // CSR column (src) indices
__device__ int   g_bsum[512];          // block sums for scan

// ---------------- degree pipeline ------------------------------------------
__global__ void k_zero_deg(int n) {
    int i = blockIdx.x * blockDim.x + threadIdx.x;
    if (i < n) g_deg[i] = 0;
}

__global__ void k_count(const int* __restrict__ dst, int E) {
    int i = blockIdx.x * blockDim.x + threadIdx.x;
    if (i < E) atomicAdd(&g_deg[dst[i]], 1);
}

// ---------------- scan1: block scan of degrees + isqrt fused ----------------
__global__ void k_scan1(int n) {
    __shared__ int sm[SCAN_B];
    int i = blockIdx.x * SCAN_B + threadIdx.x;
    int v = (i < n) ? g_deg[i] : 0;
    if (i < n) g_dis[i] = rsqrtf((float)(v + 1));   // fused isqrt (+1 self-loop)
    sm[threadIdx.x] = v;
    __syncthreads();
    int x = v;
#pragma unroll
    for (int off = 1; off < SCAN_B; off <<= 1) {
        int y = (threadIdx.x >= off) ? sm[threadIdx.x - off] : 0;
        __syncthreads();
        x += y;
        sm[threadIdx.x] = x;
        __syncthreads();
    }
    if (i < n) g_off[i] = x - v;                    // block-local exclusive
    if (threadIdx.x == SCAN_B - 1) g_bsum[blockIdx.x] = x;
}

// ---------------- scan23: each block scans block sums redundantly -----------
__global__ void k_scan23(int n, int nb) {
    __shared__ int sm[SCAN_B];
    int t = threadIdx.x;
    int v = (t < nb) ? g_bsum[t] : 0;
    sm[t] = v;
    __syncthreads();
    int x = v;
#pragma unroll
    for (int off = 1; off < SCAN_B; off <<= 1) {
        int y = (t >= off) ? sm[t - off] : 0;
        __syncthreads();
        x += y;
        sm[t] = x;
        __syncthreads();
    }
    // sm[] now inclusive; base for this block = inclusive[blockIdx.x - 1]
    int base = (blockIdx.x > 0) ? sm[blockIdx.x - 1] : 0;
    __syncthreads();  // (sm reuse safety not needed, but cheap)
    int i = blockIdx.x * SCAN_B + t;
    if (i < n) {
        int o = g_off[i] + base;
        g_off[i] = o;
        g_cur[i] = o;
    }
}

__global__ void k_fill(const int* __restrict__ src, const int* __restrict__ dst, int E) {
    int i = blockIdx.x * blockDim.x + threadIdx.x;
    if (i < E) {
        int pos = atomicAdd(&g_cur[dst[i]], 1);
        g_eidx[pos] = src[i];
    }
}

// ---------------- gather chunk: C independent neighbor loads ----------------
template <int C, int LAYER>
__device__ __forceinline__ void gather_chunk(const float* __restrict__ feat,
                                             int j, int lane, float4& acc) {
    int id[C];
#pragma unroll
    for (int u = 0; u < C; u++) id[u] = g_eidx[j + u];
    float4 v[C];
#pragma unroll
    for (int u = 0; u < C; u++)
        v[u] = ((const float4*)feat)[(size_t)id[u] * 32 + lane];
    if (LAYER == 1) {
        float sc[C];
#pragma unroll
        for (int u = 0; u < C; u++) sc[u] = g_dis[id[u]];
#pragma unroll
        for (int u = 0; u < C; u++) {
            acc.x += v[u].x * sc[u]; acc.y += v[u].y * sc[u];
            acc.z += v[u].z * sc[u]; acc.w += v[u].w * sc[u];
        }
    } else {
#pragma unroll
        for (int u = 0; u < C; u++) {
            acc.x += v[u].x; acc.y += v[u].y;
            acc.z += v[u].z; acc.w += v[u].w;
        }
    }
}

template <int LAYER>
__device__ __forceinline__ void gather_row(const float* __restrict__ feat,
                                           int beg, int end, int lane, float4& acc) {
    int j = beg;
    int rem = end - beg;
    while (rem >= 8) { gather_chunk<8, LAYER>(feat, j, lane, acc); j += 8; rem -= 8; }
    if (rem >= 4)    { gather_chunk<4, LAYER>(feat, j, lane, acc); j += 4; rem -= 4; }
    if (rem >= 2)    { gather_chunk<2, LAYER>(feat, j, lane, acc); j += 2; rem -= 2; }
    if (rem)         { gather_chunk<1, LAYER>(feat, j, lane, acc); }
}

// ---------------- layer-1 gather:  g_accX[v] = d_v*(d_v*x_v + sum d_s*x_s) --
__global__ void k_gather1(const float* __restrict__ x, int n) {
    int gtid = blockIdx.x * blockDim.x + threadIdx.x;
    int w = gtid >> 5;
    int lane = threadIdx.x & 31;
    if (w >= n) return;

    float s = g_dis[w];
    float4 acc = ((const float4*)x)[(size_t)w * 32 + lane];
    acc.x *= s; acc.y *= s; acc.z *= s; acc.w *= s;

    gather_row<1>(x, g_off[w], g_cur[w], lane, acc);

    acc.x *= s; acc.y *= s; acc.z *= s; acc.w *= s;
    ((float4*)g_accX)[(size_t)w * 32 + lane] = acc;
}

// ---------------- tf32 helpers ----------------------------------------------
__device__ __forceinline__ uint32_t f2tf(float x) {
    uint32_t r;
    asm("cvt.rna.tf32.f32 %0, %1;" : "=r"(r) : "f"(x));
    return r;
}

__device__ __forceinline__ void mma_tf32(float& c0, float& c1, float& c2, float& c3,
                                         uint32_t a0, uint32_t a1, uint32_t a2, uint32_t a3,
                                         uint32_t b0, uint32_t b1) {
    asm volatile(
        "mma.sync.aligned.m16n8k8.row.col.f32.tf32.tf32.f32 "
        "{%0,%1,%2,%3},{%4,%5,%6,%7},{%8,%9},{%0,%1,%2,%3};"
        : "+f"(c0), "+f"(c1), "+f"(c2), "+f"(c3)
        : "r"(a0), "r"(a1), "r"(a2), "r"(a3), "r"(b0), "r"(b1));
}

// ---------------- tf32 tensor-core GEMM ------------------------------------
// Block 128x128, BK=32, 256 thr = 8 warps (2 x 4), warp tile 64x32.
// MODE 1 (conv1): A = g_accX; C = relu(v + b1) -> g_h1
// MODE 2 (conv2): A = g_h1;   C = d_row * v    -> g_g2
#define GPA 137   // As row stride (floats), As[k][m]
#define GPB 136   // Bs row stride (floats), Bs[k][n]

template <int MODE>
__global__ __launch_bounds__(256, 2)
void k_gemm_tc(const float* __restrict__ Bw, const float* __restrict__ bias,
               int M, int N, int K) {
    __shared__ uint32_t As[32 * GPA];
    __shared__ uint32_t Bs[32 * GPB];

    const float* A = (MODE == 1) ? g_accX : g_h1;

    int tid  = threadIdx.x;
    int lane = tid & 31;
    int wid  = tid >> 5;
    int warp_m = wid & 1;   // 0..1 (64 rows each)
    int warp_n = wid >> 1;  // 0..3 (32 cols each)
    int bm = blockIdx.x * 128;
    int bn = blockIdx.y * 128;

    float c[4][4][4];
#pragma unroll
    for (int mt = 0; mt < 4; mt++)
#pragma unroll
        for (int nt = 0; nt < 4; nt++)
#pragma unroll
            for (int r = 0; r < 4; r++) c[mt][nt][r] = 0.f;

    int lq = lane & 3;      // threadID in quad
    int lg = lane >> 2;     // group id

    for (int k0 = 0; k0 < K; k0 += 32) {
        // --- A tile: 128 x 32 floats ---
#pragma unroll
        for (int q = 0; q < 4; q++) {
            int idx = q * 256 + tid;
            int m = idx >> 3;          // 0..127
            int k4 = idx & 7;          // 0..7
            float4 v = make_float4(0.f, 0.f, 0.f, 0.f);
            if (bm + m < M)
                v = *(const float4*)(A + (size_t)(bm + m) * K + k0 + k4 * 4);
            As[(k4 * 4 + 0) * GPA + m] = f2tf(v.x);
            As[(k4 * 4 + 1) * GPA + m] = f2tf(v.y);
            As[(k4 * 4 + 2) * GPA + m] = f2tf(v.z);
            As[(k4 * 4 + 3) * GPA + m] = f2tf(v.w);
        }
        // --- B tile: 32 x 128 floats ---
#pragma unroll
        for (int q = 0; q < 4; q++) {
            int idx = q * 256 + tid;
            int k = idx >> 5;          // 0..31
            int n4 = idx & 31;         // 0..31
            float4 v = *(const float4*)(Bw + (size_t)(k0 + k) * N + bn + n4 * 4);
            uint32_t* p = &Bs[k * GPB + n4 * 4];
            p[0] = f2tf(v.x); p[1] = f2tf(v.y); p[2] = f2tf(v.z); p[3] = f2tf(v.w);
        }
        __syncthreads();

#pragma unroll
        for (int kk = 0; kk < 4; kk++) {
            int kb = kk * 8 + lq;
            uint32_t a[4][4];
#pragma unroll
            for (int mt = 0; mt < 4; mt++) {
                int mr = warp_m * 64 + mt * 16 + lg;
                a[mt][0] = As[kb * GPA + mr];
                a[mt][1] = As[kb * GPA + mr + 8];
                a[mt][2] = As[(kb + 4) * GPA + mr];
                a[mt][3] = As[(kb + 4) * GPA + mr + 8];
            }
            uint32_t b[4][2];
#pragma unroll
            for (int nt = 0; nt < 4; nt++) {
                int nc = warp_n * 32 + nt * 8 + lg;
                b[nt][0] = Bs[kb * GPB + nc];
                b[nt][1] = Bs[(kb + 4) * GPB + nc];
            }
#pragma unroll
            for (int mt = 0; mt < 4; mt++)
#pragma unroll
                for (int nt = 0; nt < 4; nt++)
                    mma_tf32(c[mt][nt][0], c[mt][nt][1], c[mt][nt][2], c[mt][nt][3],
                             a[mt][0], a[mt][1], a[mt][2], a[mt][3],
                             b[nt][0], b[nt][1]);
        }
        __syncthreads();
    }

    // ---- epilogue ----
#pragma unroll
    for (int mt = 0; mt < 4; mt++) {
        int row0 = bm + warp_m * 64 + mt * 16 + lg;
        int row1 = row0 + 8;
#pragma unroll
        for (int nt = 0; nt < 4; nt++) {
            int col = bn + warp_n * 32 + nt * 8 + lq * 2;
            if (MODE == 1) {
                float2 bb = *(const float2*)(bias + col);
                if (row0 < M) {
                    float2 v;
                    v.x = fmaxf(c[mt][nt][0] + bb.x, 0.f);
                    v.y = fmaxf(c[mt][nt][1] + bb.y, 0.f);
                    *(float2*)(g_h1 + (size_t)row0 * N + col) = v;
                }
                if (row1 < M) {
                    float2 v;
                    v.x = fmaxf(c[mt][nt][2] + bb.x, 0.f);
                    v.y = fmaxf(c[mt][nt][3] + bb.y, 0.f);
                    *(float2*)(g_h1 + (size_t)row1 * N + col) = v;
                }
            } else {
                if (row0 < M) {
                    float s0 = g_dis[row0];
                    float2 v = make_float2(c[mt][nt][0] * s0, c[mt][nt][1] * s0);
                    *(float2*)(g_g2 + (size_t)row0 * N + col) = v;
                }
                if (row1 < M) {
                    float s1 = g_dis[row1];
                    float2 v = make_float2(c[mt][nt][2] * s1, c[mt][nt][3] * s1);
                    *(float2*)(g_g2 + (size_t)row1 * N + col) = v;
                }
            }
        }
    }
}

// ---------------- fused layer-2 gather + FC head ----------------------------
// acc = g2[v] + sum g2[s];  h = relu(d_v*acc + b2);  out = h @ Wfc + bfc
__global__ void k_gather2fc(const float* __restrict__ Wfc, const float* __restrict__ bfc,
                            const float* __restrict__ b2, float* __restrict__ out, int n) {
    int gtid = blockIdx.x * blockDim.x + threadIdx.x;
    int w = gtid >> 5;
    int lane = threadIdx.x & 31;
    if (w >= n) return;

    float4 acc = ((const float4*)g_g2)[(size_t)w * 32 + lane];
    gather_row<2>(g_g2, g_off[w], g_cur[w], lane, acc);

    float s = g_dis[w];
    float4 bb = ((const float4*)b2)[lane];
    float h[4];
    h[0] = fmaxf(acc.x * s + bb.x, 0.f);
    h[1] = fmaxf(acc.y * s + bb.y, 0.f);
    h[2] = fmaxf(acc.z * s + bb.z, 0.f);
    h[3] = fmaxf(acc.w * s + bb.w, 0.f);

    int c0 = lane * 4;
    float a6[DOUT];
#pragma unroll
    for (int o = 0; o < DOUT; o++) a6[o] = 0.f;
#pragma unroll
    for (int j = 0; j < 4; j++)
#pragma unroll
        for (int o = 0; o < DOUT; o++)
            a6[o] += h[j] * __ldg(&Wfc[(c0 + j) * DOUT + o]);
#pragma unroll
    for (int o = 0; o < DOUT; o++)
        for (int off = 16; off; off >>= 1)
            a6[o] += __shfl_xor_sync(0xffffffffu, a6[o], off);
    if (lane == 0) {
#pragma unroll
        for (int o = 0; o < DOUT; o++) out[(size_t)w * DOUT + o] = a6[o] + bfc[o];
    }
}

// ---------------- launch ----------------------------------------------------
extern "C" void kernel_launch(void* const* d_in, const int* in_sizes, int n_in,
                              void* d_out, int out_size) {
    const float* x   = (const float*)d_in[0];
    const float* W1  = (const float*)d_in[1];
    const float* b1  = (const float*)d_in[2];
    const float* W2  = (const float*)d_in[3];
    const float* b2  = (const float*)d_in[4];
    const float* Wfc = (const float*)d_in[5];
    const float* bfc = (const float*)d_in[6];
    const int*   ei  = (const int*)d_in[7];

    int n = in_sizes[0] / DIN;
    int E = in_sizes[7] / 2;
    const int* src = ei;
    const int* dst = ei + E;
    float* out = (float*)d_out;
    int nb = (n + SCAN_B - 1) / SCAN_B;

    // degrees
    k_zero_deg<<<nb, SCAN_B>>>(n);
    k_count<<<(E + 255) / 256, 256>>>(dst, E);

    // CSR build (by dst): scan1 (+isqrt), scan23, fill
    k_scan1<<<nb, SCAN_B>>>(n);
    k_scan23<<<nb, SCAN_B>>>(n, nb);
    k_fill<<<(E + 255) / 256, 256>>>(src, dst, E);

    // layer 1: gather-aggregate X, then tensor-core GEMM (128 -> 256) + relu
    k_gather1<<<(n * 32 + 255) / 256, 256>>>(x, n);
    {
        dim3 grid((n + 127) / 128, H1 / 128);
        k_gemm_tc<1><<<grid, 256>>>(W1, b1, n, H1, DIN);
    }

    // layer 2: GEMM (256 -> 128) with d_row epilogue, then fused gather + FC
    {
        dim3 grid((n + 127) / 128, H2 / 128);
        k_gemm_tc<2><<<grid, 256>>>(W2, nullptr, n, H2, H1);
    }
    k_gather2fc<<<(n * 32 + 255) / 256, 256>>>(Wfc, bfc, b2, out, n);
}

// round 8
// speedup vs baseline: 2.8459x; 1.0263x over previous
#include <cuda_runtime.h>
#include <cstdint>

#define NMAX 50000
#define EMAX 500000
#define DIN  128   // input feature dim
#define H1   256   // conv1 output dim (2 * hidden)
#define H2   128   // conv2 output dim
#define DOUT 6
#define CAP  64    // ELL bucket capacity (deg ~ Poisson(10); P(>64) ~ 1e-30)

// ---------------- scratch (device globals; no allocation allowed) ----------
__device__ float g_accX[NMAX * DIN];   // d_v * (d_v*x_v + sum d_s*x_s)
__device__ float g_h1  [NMAX * H1];    // relu(conv1 output)
__device__ float g_g2  [NMAX * H2];    // d_i * (h1 @ W2)
__device__ int   g_cnt [NMAX];         // in-degree counter / ELL cursor (self-clearing)
__device__ int   g_eidx[NMAX * CAP];   // ELL neighbor (src) indices

// ---------------- ELL fill: one pass builds adjacency + degrees -------------
__global__ void k_fill(const int* __restrict__ src, const int* __restrict__ dst, int E) {
    int i = blockIdx.x * blockDim.x + threadIdx.x;
    if (i < E) {
        int d = dst[i];
        int pos = atomicAdd(&g_cnt[d], 1);
        if (pos < CAP) g_eidx[d * CAP + pos] = src[i];
    }
}

__device__ __forceinline__ float disq(int cnt) {  // (deg+1)^{-1/2}
    return rsqrtf((float)(cnt + 1));
}

// ---------------- gather chunk: C independent neighbor loads ----------------
template <int C, int LAYER>
__device__ __forceinline__ void gather_chunk(const float* __restrict__ feat,
                                             int j, int lane, float4& acc) {
    int id[C];
#pragma unroll
    for (int u = 0; u < C; u++) id[u] = g_eidx[j + u];
    float4 v[C];
#pragma unroll
    for (int u = 0; u < C; u++)
        v[u] = ((const float4*)feat)[(size_t)id[u] * 32 + lane];
    if (LAYER == 1) {
        float sc[C];
#pragma unroll
        for (int u = 0; u < C; u++) sc[u] = disq(g_cnt[id[u]]);
#pragma unroll
        for (int u = 0; u < C; u++) {
            acc.x += v[u].x * sc[u]; acc.y += v[u].y * sc[u];
            acc.z += v[u].z * sc[u]; acc.w += v[u].w * sc[u];
        }
    } else {
#pragma unroll
        for (int u = 0; u < C; u++) {
            acc.x += v[u].x; acc.y += v[u].y;
            acc.z += v[u].z; acc.w += v[u].w;
        }
    }
}

template <int LAYER>
__device__ __forceinline__ void gather_row(const float* __restrict__ feat,
                                           int beg, int len, int lane, float4& acc) {
    int j = beg;
    int rem = len;
    while (rem >= 8) { gather_chunk<8, LAYER>(feat, j, lane, acc); j += 8; rem -= 8; }
    if (rem >= 4)    { gather_chunk<4, LAYER>(feat, j, lane, acc); j += 4; rem -= 4; }
    if (rem >= 2)    { gather_chunk<2, LAYER>(feat, j, lane, acc); j += 2; rem -= 2; }
    if (rem)         { gather_chunk<1, LAYER>(feat, j, lane, acc); }
}

// ---------------- layer-1 gather:  g_accX[v] = d_v*(d_v*x_v + sum d_s*x_s) --
__global__ void k_gather1(const float* __restrict__ x, int n) {
    int gtid = blockIdx.x * blockDim.x + threadIdx.x;
    int w = gtid >> 5;
    int lane = threadIdx.x & 31;
    if (w >= n) return;

    int cnt = g_cnt[w];
    int len = min(cnt, CAP);
    float s = disq(cnt);
    float4 acc = ((const float4*)x)[(size_t)w * 32 + lane];
    acc.x *= s; acc.y *= s; acc.z *= s; acc.w *= s;

    gather_row<1>(x, w * CAP, len, lane, acc);

    acc.x *= s; acc.y *= s; acc.z *= s; acc.w *= s;
    ((float4*)g_accX)[(size_t)w * 32 + lane] = acc;
}

// ---------------- tf32 helpers ----------------------------------------------
__device__ __forceinline__ uint32_t f2tf(float x) {
    uint32_t r;
    asm("cvt.rna.tf32.f32 %0, %1;" : "=r"(r) : "f"(x));
    return r;
}

__device__ __forceinline__ void mma_tf32(float& c0, float& c1, float& c2, float& c3,
                                         uint32_t a0, uint32_t a1, uint32_t a2, uint32_t a3,
                                         uint32_t b0, uint32_t b1) {
    asm volatile(
        "mma.sync.aligned.m16n8k8.row.col.f32.tf32.tf32.f32 "
        "{%0,%1,%2,%3},{%4,%5,%6,%7},{%8,%9},{%0,%1,%2,%3};"
        : "+f"(c0), "+f"(c1), "+f"(c2), "+f"(c3)
        : "r"(a0), "r"(a1), "r"(a2), "r"(a3), "r"(b0), "r"(b1));
}

// ---------------- tf32 tensor-core GEMM ------------------------------------
// Block 128x128, BK=32, 256 thr = 8 warps (2 x 4), warp tile 64x32.
// MODE 1 (conv1): A = g_accX; C = relu(v + b1) -> g_h1
// MODE 2 (conv2): A = g_h1;   C = d_row * v    -> g_g2
#define GPA 137   // As row stride (floats), As[k][m]
#define GPB 136   // Bs row stride (floats), Bs[k][n]

template <int MODE>
__global__ __launch_bounds__(256, 2)
void k_gemm_tc(const float* __restrict__ Bw, const float* __restrict__ bias,
               int M, int N, int K) {
    __shared__ uint32_t As[32 * GPA];
    __shared__ uint32_t Bs[32 * GPB];

    const float* A = (MODE == 1) ? g_accX : g_h1;

    int tid  = threadIdx.x;
    int lane = tid & 31;
    int wid  = tid >> 5;
    int warp_m = wid & 1;   // 0..1 (64 rows each)
    int warp_n = wid >> 1;  // 0..3 (32 cols each)
    int bm = blockIdx.x * 128;
    int bn = blockIdx.y * 128;

    float c[4][4][4];
#pragma unroll
    for (int mt = 0; mt < 4; mt++)
#pragma unroll
        for (int nt = 0; nt < 4; nt++)
#pragma unroll
            for (int r = 0; r < 4; r++) c[mt][nt][r] = 0.f;

    int lq = lane & 3;      // threadID in quad
    int lg = lane >> 2;     // group id

    for (int k0 = 0; k0 < K; k0 += 32) {
        // --- A tile: 128 x 32 floats ---
#pragma unroll
        for (int q = 0; q < 4; q++) {
            int idx = q * 256 + tid;
            int m = idx >> 3;          // 0..127
            int k4 = idx & 7;          // 0..7
            float4 v = make_float4(0.f, 0.f, 0.f, 0.f);
            if (bm + m < M)
                v = *(const float4*)(A + (size_t)(bm + m) * K + k0 + k4 * 4);
            As[(k4 * 4 + 0) * GPA + m] = f2tf(v.x);
            As[(k4 * 4 + 1) * GPA + m] = f2tf(v.y);
            As[(k4 * 4 + 2) * GPA + m] = f2tf(v.z);
            As[(k4 * 4 + 3) * GPA + m] = f2tf(v.w);
        }
        // --- B tile: 32 x 128 floats ---
#pragma unroll
        for (int q = 0; q < 4; q++) {
            int idx = q * 256 + tid;
            int k = idx >> 5;          // 0..31
            int n4 = idx & 31;         // 0..31
            float4 v = *(const float4*)(Bw + (size_t)(k0 + k) * N + bn + n4 * 4);
            uint32_t* p = &Bs[k * GPB + n4 * 4];
            p[0] = f2tf(v.x); p[1] = f2tf(v.y); p[2] = f2tf(v.z); p[3] = f2tf(v.w);
        }
        __syncthreads();

#pragma unroll
        for (int kk = 0; kk < 4; kk++) {
            int kb = kk * 8 + lq;
            uint32_t a[4][4];
#pragma unroll
            for (int mt = 0; mt < 4; mt++) {
                int mr = warp_m * 64 + mt * 16 + lg;
                a[mt][0] = As[kb * GPA + mr];
                a[mt][1] = As[kb * GPA + mr + 8];
                a[mt][2] = As[(kb + 4) * GPA + mr];
                a[mt][3] = As[(kb + 4) * GPA + mr + 8];
            }
            uint32_t b[4][2];
#pragma unroll
            for (int nt = 0; nt < 4; nt++) {
                int nc = warp_n * 32 + nt * 8 + lg;
                b[nt][0] = Bs[kb * GPB + nc];
                b[nt][1] = Bs[(kb + 4) * GPB + nc];
            }
#pragma unroll
            for (int mt = 0; mt < 4; mt++)
#pragma unroll
                for (int nt = 0; nt < 4; nt++)
                    mma_tf32(c[mt][nt][0], c[mt][nt][1], c[mt][nt][2], c[mt][nt][3],
                             a[mt][0], a[mt][1], a[mt][2], a[mt][3],
                             b[nt][0], b[nt][1]);
        }
        __syncthreads();
    }

    // ---- epilogue ----
#pragma unroll
    for (int mt = 0; mt < 4; mt++) {
        int row0 = bm + warp_m * 64 + mt * 16 + lg;
        int row1 = row0 + 8;
#pragma unroll
        for (int nt = 0; nt < 4; nt++) {
            int col = bn + warp_n * 32 + nt * 8 + lq * 2;
            if (MODE == 1) {
                float2 bb = *(const float2*)(bias + col);
                if (row0 < M) {
                    float2 v;
                    v.x = fmaxf(c[mt][nt][0] + bb.x, 0.f);
                    v.y = fmaxf(c[mt][nt][1] + bb.y, 0.f);
                    *(float2*)(g_h1 + (size_t)row0 * N + col) = v;
                }
                if (row1 < M) {
                    float2 v;
                    v.x = fmaxf(c[mt][nt][2] + bb.x, 0.f);
                    v.y = fmaxf(c[mt][nt][3] + bb.y, 0.f);
                    *(float2*)(g_h1 + (size_t)row1 * N + col) = v;
                }
            } else {
                if (row0 < M) {
                    float s0 = disq(g_cnt[row0]);
                    float2 v = make_float2(c[mt][nt][0] * s0, c[mt][nt][1] * s0);
                    *(float2*)(g_g2 + (size_t)row0 * N + col) = v;
                }
                if (row1 < M) {
                    float s1 = disq(g_cnt[row1]);
                    float2 v = make_float2(c[mt][nt][2] * s1, c[mt][nt][3] * s1);
                    *(float2*)(g_g2 + (size_t)row1 * N + col) = v;
                }
            }
        }
    }
}

// ---------------- fused layer-2 gather + FC head (also clears g_cnt) --------
// acc = g2[v] + sum g2[s];  h = relu(d_v*acc + b2);  out = h @ Wfc + bfc
__global__ void k_gather2fc(const float* __restrict__ Wfc, const float* __restrict__ bfc,
                            const float* __restrict__ b2, float* __restrict__ out, int n) {
    int gtid = blockIdx.x * blockDim.x + threadIdx.x;
    int w = gtid >> 5;
    int lane = threadIdx.x & 31;
    if (w >= n) return;

    int cnt = g_cnt[w];
    int len = min(cnt, CAP);
    float s = disq(cnt);

    float4 acc = ((const float4*)g_g2)[(size_t)w * 32 + lane];
    gather_row<2>(g_g2, w * CAP, len, lane, acc);

    // self-clear degree counter for the next graph replay
    if (lane == 0) g_cnt[w] = 0;

    float4 bb = ((const float4*)b2)[lane];
    float h[4];
    h[0] = fmaxf(acc.x * s + bb.x, 0.f);
    h[1] = fmaxf(acc.y * s + bb.y, 0.f);
    h[2] = fmaxf(acc.z * s + bb.z, 0.f);
    h[3] = fmaxf(acc.w * s + bb.w, 0.f);

    int c0 = lane * 4;
    float a6[DOUT];
#pragma unroll
    for (int o = 0; o < DOUT; o++) a6[o] = 0.f;
#pragma unroll
    for (int j = 0; j < 4; j++)
#pragma unroll
        for (int o = 0; o < DOUT; o++)
            a6[o] += h[j] * __ldg(&Wfc[(c0 + j) * DOUT + o]);
#pragma unroll
    for (int o = 0; o < DOUT; o++)
        for (int off = 16; off; off >>= 1)
            a6[o] += __shfl_xor_sync(0xffffffffu, a6[o], off);
    if (lane == 0) {
#pragma unroll
        for (int o = 0; o < DOUT; o++) out[(size_t)w * DOUT + o] = a6[o] + bfc[o];
    }
}

// ---------------- launch ----------------------------------------------------
extern "C" void kernel_launch(void* const* d_in, const int* in_sizes, int n_in,
                              void* d_out, int out_size) {
    const float* x   = (const float*)d_in[0];
    const float* W1  = (const float*)d_in[1];
    const float* b1  = (const float*)d_in[2];
    const float* W2  = (const float*)d_in[3];
    const float* b2  = (const float*)d_in[4];
    const float* Wfc = (const float*)d_in[5];
    const float* bfc = (const float*)d_in[6];
    const int*   ei  = (const int*)d_in[7];

    int n = in_sizes[0] / DIN;
    int E = in_sizes[7] / 2;
    const int* src = ei;
    const int* dst = ei + E;
    float* out = (float*)d_out;

    // 1. ELL adjacency + degrees in one pass (g_cnt starts zero: static init +
    //    self-cleared by k_gather2fc at the end of every call)
    k_fill<<<(E + 255) / 256, 256>>>(src, dst, E);

    // 2. layer-1 gather-aggregate
    k_gather1<<<(n * 32 + 255) / 256, 256>>>(x, n);

    // 3. GEMM1 (128 -> 256) + bias + relu
    {
        dim3 grid((n + 127) / 128, H1 / 128);
        k_gemm_tc<1><<<grid, 256>>>(W1, b1, n, H1, DIN);
    }

    // 4. GEMM2 (256 -> 128) with d_row epilogue
    {
        dim3 grid((n + 127) / 128, H2 / 128);
        k_gemm_tc<2><<<grid, 256>>>(W2, nullptr, n, H2, H1);
    }

    // 5. fused layer-2 gather + FC head (+ counter clear)
    k_gather2fc<<<(n * 32 + 255) / 256, 256>>>(Wfc, bfc, b2, out, n);
}

// round 9
// speedup vs baseline: 3.0107x; 1.0579x over previous
#include <cuda_runtime.h>
#include <cstdint>

#define NMAX 50000
#define EMAX 500000
#define DIN  128   // input feature dim
#define H1   256   // conv1 output dim (2 * hidden)
#define H2   128   // conv2 output dim
#define DOUT 6
#define CAP  64    // ELL bucket capacity (deg ~ Poisson(10); P(>64) ~ 1e-30)

#define ASTR 20    // As row stride (floats): bank = (20*lg+lq)%32 all-distinct
#define BSTR 136   // Bs row stride (floats): bank = (8*lq+lg)%32 all-distinct

// ---------------- scratch (device globals; no allocation allowed) ----------
__device__ float g_accX[NMAX * DIN];   // tf32-rounded aggregate (GEMM1 A)
__device__ float g_h1  [NMAX * H1];    // tf32-rounded relu(conv1) (GEMM2 A)
__device__ float g_g2  [NMAX * H2];    // d_i * (h1 @ W2), full f32
__device__ float g_W1r [DIN * H1];     // tf32-rounded W1
__device__ float g_W2r [H1 * H2];      // tf32-rounded W2
__device__ int   g_cnt [NMAX];         // in-degree counter (self-clearing)
__device__ int   g_eidx[NMAX * CAP];   // ELL neighbor (src) indices

// ---------------- tf32 helpers ----------------------------------------------
__device__ __forceinline__ uint32_t f2tf(float x) {
    uint32_t r;
    asm("cvt.rna.tf32.f32 %0, %1;" : "=r"(r) : "f"(x));
    return r;
}
__device__ __forceinline__ float rtf(float x) { return __uint_as_float(f2tf(x)); }

// ---------------- weight rounding (tiny prep) --------------------------------
__global__ void k_round(const float* __restrict__ W1, const float* __restrict__ W2) {
    int i = blockIdx.x * blockDim.x + threadIdx.x;
    if (i < DIN * H1) g_W1r[i] = rtf(W1[i]);
    if (i < H1 * H2)  g_W2r[i] = rtf(W2[i]);
}

// ---------------- ELL fill: one pass builds adjacency + degrees -------------
__global__ void k_fill(const int* __restrict__ src, const int* __restrict__ dst, int E) {
    int i = blockIdx.x * blockDim.x + threadIdx.x;
    if (i < E) {
        int d = dst[i];
        int pos = atomicAdd(&g_cnt[d], 1);
        if (pos < CAP) g_eidx[d * CAP + pos] = src[i];
    }
}

__device__ __forceinline__ float disq(int cnt) {  // (deg+1)^{-1/2}
    return rsqrtf((float)(cnt + 1));
}

// ---------------- gather chunk: C independent neighbor loads ----------------
template <int C, int LAYER>
__device__ __forceinline__ void gather_chunk(const float* __restrict__ feat,
                                             int j, int lane, float4& acc) {
    int id[C];
#pragma unroll
    for (int u = 0; u < C; u++) id[u] = g_eidx[j + u];
    float4 v[C];
#pragma unroll
    for (int u = 0; u < C; u++)
        v[u] = ((const float4*)feat)[(size_t)id[u] * 32 + lane];
    if (LAYER == 1) {
        float sc[C];
#pragma unroll
        for (int u = 0; u < C; u++) sc[u] = disq(g_cnt[id[u]]);
#pragma unroll
        for (int u = 0; u < C; u++) {
            acc.x += v[u].x * sc[u]; acc.y += v[u].y * sc[u];
            acc.z += v[u].z * sc[u]; acc.w += v[u].w * sc[u];
        }
    } else {
#pragma unroll
        for (int u = 0; u < C; u++) {
            acc.x += v[u].x; acc.y += v[u].y;
            acc.z += v[u].z; acc.w += v[u].w;
        }
    }
}

template <int LAYER>
__device__ __forceinline__ void gather_row(const float* __restrict__ feat,
                                           int beg, int len, int lane, float4& acc) {
    int j = beg;
    int rem = len;
    while (rem >= 8) { gather_chunk<8, LAYER>(feat, j, lane, acc); j += 8; rem -= 8; }
    if (rem >= 4)    { gather_chunk<4, LAYER>(feat, j, lane, acc); j += 4; rem -= 4; }
    if (rem >= 2)    { gather_chunk<2, LAYER>(feat, j, lane, acc); j += 2; rem -= 2; }
    if (rem)         { gather_chunk<1, LAYER>(feat, j, lane, acc); }
}

// ---------------- layer-1 gather (output tf32-rounded) ----------------------
__global__ void k_gather1(const float* __restrict__ x, int n) {
    int gtid = blockIdx.x * blockDim.x + threadIdx.x;
    int w = gtid >> 5;
    int lane = threadIdx.x & 31;
    if (w >= n) return;

    int cnt = g_cnt[w];
    int len = min(cnt, CAP);
    float s = disq(cnt);
    float4 acc = ((const float4*)x)[(size_t)w * 32 + lane];
    acc.x *= s; acc.y *= s; acc.z *= s; acc.w *= s;

    gather_row<1>(x, w * CAP, len, lane, acc);

    float4 o;
    o.x = rtf(acc.x * s); o.y = rtf(acc.y * s);
    o.z = rtf(acc.z * s); o.w = rtf(acc.w * s);
    ((float4*)g_accX)[(size_t)w * 32 + lane] = o;
}

// ---------------- cp.async helpers -------------------------------------------
__device__ __forceinline__ void cpa16(float* dst, const float* src, int srcbytes) {
    uint32_t d = (uint32_t)__cvta_generic_to_shared(dst);
    asm volatile("cp.async.cg.shared.global [%0], [%1], 16, %2;"
                 :: "r"(d), "l"(src), "r"(srcbytes));
}
__device__ __forceinline__ void cpa_commit() {
    asm volatile("cp.async.commit_group;");
}
template <int N>
__device__ __forceinline__ void cpa_wait() {
    asm volatile("cp.async.wait_group %0;" :: "n"(N));
}

__device__ __forceinline__ void mma_tf32(float& c0, float& c1, float& c2, float& c3,
                                         uint32_t a0, uint32_t a1, uint32_t a2, uint32_t a3,
                                         uint32_t b0, uint32_t b1) {
    asm volatile(
        "mma.sync.aligned.m16n8k8.row.col.f32.tf32.tf32.f32 "
        "{%0,%1,%2,%3},{%4,%5,%6,%7},{%8,%9},{%0,%1,%2,%3};"
        : "+f"(c0), "+f"(c1), "+f"(c2), "+f"(c3)
        : "r"(a0), "r"(a1), "r"(a2), "r"(a3), "r"(b0), "r"(b1));
}

// ---------------- tf32 tensor-core GEMM (cp.async double-buffered) ----------
// Block 128x128, BK=16, 256 thr = 8 warps (2 x 4), warp tile 64x32.
// Inputs are pre-rounded to tf32; mma truncation is then exact.
// MODE 1 (conv1): A = g_accX, B = g_W1r; C = rtf(relu(v + b1)) -> g_h1
// MODE 2 (conv2): A = g_h1,   B = g_W2r; C = d_row * v         -> g_g2
template <int MODE>
__global__ __launch_bounds__(256, 2)
void k_gemm_tc(const float* __restrict__ bias, int M, int N, int K) {
    __shared__ float As[2][128 * ASTR];
    __shared__ float Bs[2][16 * BSTR];

    const float* A  = (MODE == 1) ? g_accX : g_h1;
    const float* Bw = (MODE == 1) ? g_W1r  : g_W2r;

    int tid  = threadIdx.x;
    int lane = tid & 31;
    int wid  = tid >> 5;
    int warp_m = wid & 1;   // 0..1 (64 rows each)
    int warp_n = wid >> 1;  // 0..3 (32 cols each)
    int bm = blockIdx.x * 128;
    int bn = blockIdx.y * 128;
    int lq = lane & 3;      // thread in quad
    int lg = lane >> 2;     // group id

    float c[4][4][4];
#pragma unroll
    for (int mt = 0; mt < 4; mt++)
#pragma unroll
        for (int nt = 0; nt < 4; nt++)
#pragma unroll
            for (int r = 0; r < 4; r++) c[mt][nt][r] = 0.f;

    int nk = K / 16;

    // ---- tile loader: stage kt into buffer bf ----
    auto load_tile = [&](int kt, int bf) {
        // A: 128 rows x 16 floats = 512 x 16B chunks
#pragma unroll
        for (int q = 0; q < 2; q++) {
            int idx = q * 256 + tid;
            int m  = idx >> 2;      // 0..127
            int k4 = idx & 3;       // 0..3
            int gr = bm + m;
            int ok = (gr < M) ? 16 : 0;
            const float* src = A + (size_t)min(gr, M - 1) * K + kt * 16 + k4 * 4;
            cpa16(&As[bf][m * ASTR + k4 * 4], src, ok);
        }
        // B: 16 rows x 128 floats = 512 x 16B chunks
#pragma unroll
        for (int q = 0; q < 2; q++) {
            int idx = q * 256 + tid;
            int k  = idx >> 5;      // 0..15
            int n4 = idx & 31;      // 0..31
            cpa16(&Bs[bf][k * BSTR + n4 * 4],
                  Bw + (size_t)(kt * 16 + k) * N + bn + n4 * 4, 16);
        }
    };

    load_tile(0, 0);
    cpa_commit();

    for (int kt = 0; kt < nk; kt++) {
        int bf = kt & 1;
        if (kt + 1 < nk) load_tile(kt + 1, bf ^ 1);
        cpa_commit();          // uniform commit (possibly empty group)
        cpa_wait<1>();         // tile kt resident
        __syncthreads();

#pragma unroll
        for (int kk = 0; kk < 2; kk++) {
            int kb = kk * 8 + lq;
            uint32_t a[4][4];
#pragma unroll
            for (int mt = 0; mt < 4; mt++) {
                int mr = warp_m * 64 + mt * 16 + lg;
                a[mt][0] = __float_as_uint(As[bf][mr * ASTR + kb]);
                a[mt][1] = __float_as_uint(As[bf][(mr + 8) * ASTR + kb]);
                a[mt][2] = __float_as_uint(As[bf][mr * ASTR + kb + 4]);
                a[mt][3] = __float_as_uint(As[bf][(mr + 8) * ASTR + kb + 4]);
            }
            uint32_t b[4][2];
#pragma unroll
            for (int nt = 0; nt < 4; nt++) {
                int nc = warp_n * 32 + nt * 8 + lg;
                b[nt][0] = __float_as_uint(Bs[bf][kb * BSTR + nc]);
                b[nt][1] = __float_as_uint(Bs[bf][(kb + 4) * BSTR + nc]);
            }
#pragma unroll
            for (int mt = 0; mt < 4; mt++)
#pragma unroll
                for (int nt = 0; nt < 4; nt++)
                    mma_tf32(c[mt][nt][0], c[mt][nt][1], c[mt][nt][2], c[mt][nt][3],
                             a[mt][0], a[mt][1], a[mt][2], a[mt][3],
                             b[nt][0], b[nt][1]);
        }
        __syncthreads();
    }

    // ---- epilogue ----
#pragma unroll
    for (int mt = 0; mt < 4; mt++) {
        int row0 = bm + warp_m * 64 + mt * 16 + lg;
        int row1 = row0 + 8;
#pragma unroll
        for (int nt = 0; nt < 4; nt++) {
            int col = bn + warp_n * 32 + nt * 8 + lq * 2;
            if (MODE == 1) {
                float2 bb = *(const float2*)(bias + col);
                if (row0 < M) {
                    float2 v;
                    v.x = rtf(fmaxf(c[mt][nt][0] + bb.x, 0.f));
                    v.y = rtf(fmaxf(c[mt][nt][1] + bb.y, 0.f));
                    *(float2*)(g_h1 + (size_t)row0 * N + col) = v;
                }
                if (row1 < M) {
                    float2 v;
                    v.x = rtf(fmaxf(c[mt][nt][2] + bb.x, 0.f));
                    v.y = rtf(fmaxf(c[mt][nt][3] + bb.y, 0.f));
                    *(float2*)(g_h1 + (size_t)row1 * N + col) = v;
                }
            } else {
                if (row0 < M) {
                    float s0 = disq(g_cnt[row0]);
                    float2 v = make_float2(c[mt][nt][0] * s0, c[mt][nt][1] * s0);
                    *(float2*)(g_g2 + (size_t)row0 * N + col) = v;
                }
                if (row1 < M) {
                    float s1 = disq(g_cnt[row1]);
                    float2 v = make_float2(c[mt][nt][2] * s1, c[mt][nt][3] * s1);
                    *(float2*)(g_g2 + (size_t)row1 * N + col) = v;
                }
            }
        }
    }
}

// ---------------- fused layer-2 gather + FC head (also clears g_cnt) --------
__global__ void k_gather2fc(const float* __restrict__ Wfc, const float* __restrict__ bfc,
                            const float* __restrict__ b2, float* __restrict__ out, int n) {
    int gtid = blockIdx.x * blockDim.x + threadIdx.x;
    int w = gtid >> 5;
    int lane = threadIdx.x & 31;
    if (w >= n) return;

    int cnt = g_cnt[w];
    int len = min(cnt, CAP);
    float s = disq(cnt);

    float4 acc = ((const float4*)g_g2)[(size_t)w * 32 + lane];
    gather_row<2>(g_g2, w * CAP, len, lane, acc);

    if (lane == 0) g_cnt[w] = 0;   // self-clear for next replay

    float4 bb = ((const float4*)b2)[lane];
    float h[4];
    h[0] = fmaxf(acc.x * s + bb.x, 0.f);
    h[1] = fmaxf(acc.y * s + bb.y, 0.f);
    h[2] = fmaxf(acc.z * s + bb.z, 0.f);
    h[3] = fmaxf(acc.w * s + bb.w, 0.f);

    int c0 = lane * 4;
    float a6[DOUT];
#pragma unroll
    for (int o = 0; o < DOUT; o++) a6[o] = 0.f;
#pragma unroll
    for (int j = 0; j < 4; j++)
#pragma unroll
        for (int o = 0; o < DOUT; o++)
            a6[o] += h[j] * __ldg(&Wfc[(c0 + j) * DOUT + o]);
#pragma unroll
    for (int o = 0; o < DOUT; o++)
        for (int off = 16; off; off >>= 1)
            a6[o] += __shfl_xor_sync(0xffffffffu, a6[o], off);
    if (lane == 0) {
#pragma unroll
        for (int o = 0; o < DOUT; o++) out[(size_t)w * DOUT + o] = a6[o] + bfc[o];
    }
}

// ---------------- launch ----------------------------------------------------
extern "C" void kernel_launch(void* const* d_in, const int* in_sizes, int n_in,
                              void* d_out, int out_size) {
    const float* x   = (const float*)d_in[0];
    const float* W1  = (const float*)d_in[1];
    const float* b1  = (const float*)d_in[2];
    const float* W2  = (const float*)d_in[3];
    const float* b2  = (const float*)d_in[4];
    const float* Wfc = (const float*)d_in[5];
    const float* bfc = (const float*)d_in[6];
    const int*   ei  = (const int*)d_in[7];

    int n = in_sizes[0] / DIN;
    int E = in_sizes[7] / 2;
    const int* src = ei;
    const int* dst = ei + E;
    float* out = (float*)d_out;

    // weight rounding + adjacency build
    k_round<<<(H1 * H2 + 255) / 256, 256>>>(W1, W2);
    k_fill<<<(E + 255) / 256, 256>>>(src, dst, E);

    // layer 1
    k_gather1<<<(n * 32 + 255) / 256, 256>>>(x, n);
    {
        dim3 grid((n + 127) / 128, H1 / 128);
        k_gemm_tc<1><<<grid, 256>>>(b1, n, H1, DIN);
    }

    // layer 2
    {
        dim3 grid((n + 127) / 128, H2 / 128);
        k_gemm_tc<2><<<grid, 256>>>(nullptr, n, H2, H1);
    }
    k_gather2fc<<<(n * 32 + 255) / 256, 256>>>(Wfc, bfc, b2, out, n);
}

// round 10
// speedup vs baseline: 3.3178x; 1.1020x over previous
#include <cuda_runtime.h>
#include <cuda_fp16.h>
#include <cstdint>

#define NMAX 50000
#define EMAX 500000
#define DIN  128   // input feature dim
#define H1   256   // conv1 output dim
#define H2   128   // conv2 output dim
#define DOUT 6
#define CAP  64    // ELL bucket capacity

#define ASTRH 24   // As row stride in halves (16 + 8 pad; 48B rows, 16B-aligned)
#define BSTRH 24   // Bs row stride in halves

// ---------------- scratch (device globals; no allocation allowed) ----------
__device__ __half g_xh  [NMAX * DIN];   // x in fp16
__device__ __half g_accX[NMAX * DIN];   // layer-1 aggregate, fp16 (GEMM1 A)
__device__ __half g_h1  [NMAX * H1];    // relu(conv1), fp16 (GEMM2 A)
__device__ float  g_g2  [NMAX * H2];    // d_i*(h1@W2), f32 (precision-critical)
__device__ __half g_W1h [H1 * DIN];     // W1 transposed [n][k], fp16
__device__ __half g_W2h [H2 * H1];      // W2 transposed [n][k], fp16
__device__ int    g_cnt [NMAX];         // in-degree counter (self-clearing)
__device__ int    g_eidx[NMAX * CAP];   // ELL neighbor (src) indices

// ---------------- prep: x -> fp16 -------------------------------------------
__global__ void k_xhalf(const float* __restrict__ x, int n) {
    int i = blockIdx.x * blockDim.x + threadIdx.x;   // float4 index
    if (i >= n * 32) return;
    float4 v = ((const float4*)x)[i];
    __half2 h0 = __floats2half2_rn(v.x, v.y);
    __half2 h1 = __floats2half2_rn(v.z, v.w);
    uint2 o;
    o.x = *reinterpret_cast<const unsigned*>(&h0);
    o.y = *reinterpret_cast<const unsigned*>(&h1);
    ((uint2*)g_xh)[i] = o;
}

// ---------------- prep: weights -> fp16, transposed to [n][k] ---------------
__global__ void k_round(const float* __restrict__ W1, const float* __restrict__ W2) {
    int i = blockIdx.x * blockDim.x + threadIdx.x;
    if (i < DIN * H1) {
        int k = i / H1, nn = i % H1;
        g_W1h[nn * DIN + k] = __float2half_rn(W1[i]);
    }
    if (i < H1 * H2) {
        int k = i / H2, nn = i % H2;
        g_W2h[nn * H1 + k] = __float2half_rn(W2[i]);
    }
}

// ---------------- ELL fill ---------------------------------------------------
__global__ void k_fill(const int* __restrict__ src, const int* __restrict__ dst, int E) {
    int i = blockIdx.x * blockDim.x + threadIdx.x;
    if (i < E) {
        int d = dst[i];
        int pos = atomicAdd(&g_cnt[d], 1);
        if (pos < CAP) g_eidx[d * CAP + pos] = src[i];
    }
}

__device__ __forceinline__ float disq(int cnt) {  // (deg+1)^{-1/2}
    return rsqrtf((float)(cnt + 1));
}

// ---------------- gather chunks ----------------------------------------------
// fp16 features (layer 1, with per-source scale)
template <int C>
__device__ __forceinline__ void gather_chunk_h(const __half* __restrict__ feat,
                                               int j, int lane, float4& acc) {
    int id[C];
#pragma unroll
    for (int u = 0; u < C; u++) id[u] = g_eidx[j + u];
    uint2 v[C];
#pragma unroll
    for (int u = 0; u < C; u++)
        v[u] = ((const uint2*)feat)[(size_t)id[u] * 32 + lane];
    float sc[C];
#pragma unroll
    for (int u = 0; u < C; u++) sc[u] = disq(g_cnt[id[u]]);
#pragma unroll
    for (int u = 0; u < C; u++) {
        float2 p0 = __half22float2(*reinterpret_cast<__half2*>(&v[u].x));
        float2 p1 = __half22float2(*reinterpret_cast<__half2*>(&v[u].y));
        acc.x += p0.x * sc[u]; acc.y += p0.y * sc[u];
        acc.z += p1.x * sc[u]; acc.w += p1.y * sc[u];
    }
}

__device__ __forceinline__ void gather_row_h(const __half* __restrict__ feat,
                                             int beg, int len, int lane, float4& acc) {
    int j = beg, rem = len;
    while (rem >= 8) { gather_chunk_h<8>(feat, j, lane, acc); j += 8; rem -= 8; }
    if (rem >= 4)    { gather_chunk_h<4>(feat, j, lane, acc); j += 4; rem -= 4; }
    if (rem >= 2)    { gather_chunk_h<2>(feat, j, lane, acc); j += 2; rem -= 2; }
    if (rem)         { gather_chunk_h<1>(feat, j, lane, acc); }
}

// f32 features (layer 2, unscaled)
template <int C>
__device__ __forceinline__ void gather_chunk_f(const float* __restrict__ feat,
                                               int j, int lane, float4& acc) {
    int id[C];
#pragma unroll
    for (int u = 0; u < C; u++) id[u] = g_eidx[j + u];
    float4 v[C];
#pragma unroll
    for (int u = 0; u < C; u++)
        v[u] = ((const float4*)feat)[(size_t)id[u] * 32 + lane];
#pragma unroll
    for (int u = 0; u < C; u++) {
        acc.x += v[u].x; acc.y += v[u].y; acc.z += v[u].z; acc.w += v[u].w;
    }
}

__device__ __forceinline__ void gather_row_f(const float* __restrict__ feat,
                                             int beg, int len, int lane, float4& acc) {
    int j = beg, rem = len;
    while (rem >= 8) { gather_chunk_f<8>(feat, j, lane, acc); j += 8; rem -= 8; }
    if (rem >= 4)    { gather_chunk_f<4>(feat, j, lane, acc); j += 4; rem -= 4; }
    if (rem >= 2)    { gather_chunk_f<2>(feat, j, lane, acc); j += 2; rem -= 2; }
    if (rem)         { gather_chunk_f<1>(feat, j, lane, acc); }
}

// ---------------- layer-1 gather (fp16 in, fp16 out) ------------------------
__global__ void k_gather1(int n) {
    int gtid = blockIdx.x * blockDim.x + threadIdx.x;
    int w = gtid >> 5;
    int lane = threadIdx.x & 31;
    if (w >= n) return;

    int cnt = g_cnt[w];
    int len = min(cnt, CAP);
    float s = disq(cnt);

    uint2 xv = ((const uint2*)g_xh)[(size_t)w * 32 + lane];
    float2 p0 = __half22float2(*reinterpret_cast<__half2*>(&xv.x));
    float2 p1 = __half22float2(*reinterpret_cast<__half2*>(&xv.y));
    float4 acc = make_float4(p0.x * s, p0.y * s, p1.x * s, p1.y * s);

    gather_row_h(g_xh, w * CAP, len, lane, acc);

    __half2 o0 = __floats2half2_rn(acc.x * s, acc.y * s);
    __half2 o1 = __floats2half2_rn(acc.z * s, acc.w * s);
    uint2 o;
    o.x = *reinterpret_cast<const unsigned*>(&o0);
    o.y = *reinterpret_cast<const unsigned*>(&o1);
    ((uint2*)g_accX)[(size_t)w * 32 + lane] = o;
}

// ---------------- cp.async helpers ------------------------------------------
__device__ __forceinline__ void cpa16h(__half* dst, const __half* src, int srcbytes) {
    uint32_t d = (uint32_t)__cvta_generic_to_shared(dst);
    asm volatile("cp.async.cg.shared.global [%0], [%1], 16, %2;"
                 :: "r"(d), "l"(src), "r"(srcbytes));
}
__device__ __forceinline__ void cpa_commit() {
    asm volatile("cp.async.commit_group;");
}
template <int N>
__device__ __forceinline__ void cpa_wait() {
    asm volatile("cp.async.wait_group %0;" :: "n"(N));
}

__device__ __forceinline__ void mma_f16(float& c0, float& c1, float& c2, float& c3,
                                        uint32_t a0, uint32_t a1, uint32_t a2, uint32_t a3,
                                        uint32_t b0, uint32_t b1) {
    asm volatile(
        "mma.sync.aligned.m16n8k16.row.col.f32.f16.f16.f32 "
        "{%0,%1,%2,%3},{%4,%5,%6,%7},{%8,%9},{%0,%1,%2,%3};"
        : "+f"(c0), "+f"(c1), "+f"(c2), "+f"(c3)
        : "r"(a0), "r"(a1), "r"(a2), "r"(a3), "r"(b0), "r"(b1));
}

// ---------------- fp16 tensor-core GEMM (3-stage cp.async, 1 barrier/stage) -
// Block 128x128, BK=16, 256 thr = 8 warps (2 x 4), warp tile 64x32.
// A [m][k] fp16 rows; B pre-transposed [n][k] fp16 rows. C = A @ B^T.
// MODE 1 (conv1): A=g_accX, B=g_W1h; C = half(relu(v+b1)) -> g_h1
// MODE 2 (conv2): A=g_h1,   B=g_W2h; C = d_row * v (f32)  -> g_g2
template <int MODE>
__global__ __launch_bounds__(256, 2)
void k_gemm_h(const float* __restrict__ bias, int M, int N, int K) {
    __shared__ __half As[3][128 * ASTRH];
    __shared__ __half Bs[3][128 * BSTRH];

    const __half* A  = (MODE == 1) ? g_accX : g_h1;
    const __half* Bw = (MODE == 1) ? g_W1h  : g_W2h;

    int tid  = threadIdx.x;
    int lane = tid & 31;
    int wid  = tid >> 5;
    int warp_m = wid & 1;   // 0..1 (64 rows)
    int warp_n = wid >> 1;  // 0..3 (32 cols)
    int bm = blockIdx.x * 128;
    int bn = blockIdx.y * 128;
    int lq = lane & 3;      // thread in quad (t)
    int lg = lane >> 2;     // group id (q)

    float c[4][4][4];
#pragma unroll
    for (int mt = 0; mt < 4; mt++)
#pragma unroll
        for (int nt = 0; nt < 4; nt++)
#pragma unroll
            for (int r = 0; r < 4; r++) c[mt][nt][r] = 0.f;

    int nk = K / 16;

    // per-thread tile chunk: 256 chunks of 16B each for A and B
    int cm  = tid >> 1;     // row 0..127
    int ck  = tid & 1;      // 16B chunk within 32B row
    int grA = bm + cm;
    const __half* srcA0 = A  + (size_t)min(grA, M - 1) * K + ck * 8;
    const __half* srcB0 = Bw + (size_t)(bn + cm) * K + ck * 8;
    int okA = (grA < M) ? 16 : 0;

    auto load_tile = [&](int kt, int bf) {
        cpa16h(&As[bf][cm * ASTRH + ck * 8], srcA0 + kt * 16, okA);
        cpa16h(&Bs[bf][cm * BSTRH + ck * 8], srcB0 + kt * 16, 16);
    };

    load_tile(0, 0); cpa_commit();
    load_tile(1, 1); cpa_commit();

    for (int kt = 0; kt < nk; kt++) {
        int bf = kt - (kt / 3) * 3;          // kt % 3
        cpa_wait<1>();                       // tile kt complete (this thread)
        __syncthreads();                     // visibility + WAR protection
        if (kt + 2 < nk) load_tile(kt + 2, (kt + 2) % 3);
        cpa_commit();                        // uniform group count

        // compute tile kt from buffer bf
        uint32_t a[4][4];
#pragma unroll
        for (int mt = 0; mt < 4; mt++) {
            int mr = warp_m * 64 + mt * 16 + lg;
            const __half* pa = &As[bf][mr * ASTRH + 2 * lq];
            a[mt][0] = *(const uint32_t*)(pa);
            a[mt][1] = *(const uint32_t*)(pa + 8 * ASTRH);
            a[mt][2] = *(const uint32_t*)(pa + 8);
            a[mt][3] = *(const uint32_t*)(pa + 8 * ASTRH + 8);
        }
        uint32_t b[4][2];
#pragma unroll
        for (int nt = 0; nt < 4; nt++) {
            int nc = warp_n * 32 + nt * 8 + lg;
            const __half* pb = &Bs[bf][nc * BSTRH + 2 * lq];
            b[nt][0] = *(const uint32_t*)(pb);
            b[nt][1] = *(const uint32_t*)(pb + 8);
        }
#pragma unroll
        for (int mt = 0; mt < 4; mt++)
#pragma unroll
            for (int nt = 0; nt < 4; nt++)
                mma_f16(c[mt][nt][0], c[mt][nt][1], c[mt][nt][2], c[mt][nt][3],
                        a[mt][0], a[mt][1], a[mt][2], a[mt][3],
                        b[nt][0], b[nt][1]);
    }

    // ---- epilogue ----
#pragma unroll
    for (int mt = 0; mt < 4; mt++) {
        int row0 = bm + warp_m * 64 + mt * 16 + lg;
        int row1 = row0 + 8;
#pragma unroll
        for (int nt = 0; nt < 4; nt++) {
            int col = bn + warp_n * 32 + nt * 8 + lq * 2;
            if (MODE == 1) {
                float2 bb = *(const float2*)(bias + col);
                if (row0 < M) {
                    __half2 v = __floats2half2_rn(fmaxf(c[mt][nt][0] + bb.x, 0.f),
                                                  fmaxf(c[mt][nt][1] + bb.y, 0.f));
                    *(unsigned*)(g_h1 + (size_t)row0 * N + col) =
                        *reinterpret_cast<const unsigned*>(&v);
                }
                if (row1 < M) {
                    __half2 v = __floats2half2_rn(fmaxf(c[mt][nt][2] + bb.x, 0.f),
                                                  fmaxf(c[mt][nt][3] + bb.y, 0.f));
                    *(unsigned*)(g_h1 + (size_t)row1 * N + col) =
                        *reinterpret_cast<const unsigned*>(&v);
                }
            } else {
                if (row0 < M) {
                    float s0 = disq(g_cnt[row0]);
                    float2 v = make_float2(c[mt][nt][0] * s0, c[mt][nt][1] * s0);
                    *(float2*)(g_g2 + (size_t)row0 * N + col) = v;
                }
                if (row1 < M) {
                    float s1 = disq(g_cnt[row1]);
                    float2 v = make_float2(c[mt][nt][2] * s1, c[mt][nt][3] * s1);
                    *(float2*)(g_g2 + (size_t)row1 * N + col) = v;
                }
            }
        }
    }
}

// ---------------- fused layer-2 gather + FC head (clears g_cnt) -------------
__global__ void k_gather2fc(const float* __restrict__ Wfc, const float* __restrict__ bfc,
                            const float* __restrict__ b2, float* __restrict__ out, int n) {
    int gtid = blockIdx.x * blockDim.x + threadIdx.x;
    int w = gtid >> 5;
    int lane = threadIdx.x & 31;
    if (w >= n) return;

    int cnt = g_cnt[w];
    int len = min(cnt, CAP);
    float s = disq(cnt);

    float4 acc = ((const float4*)g_g2)[(size_t)w * 32 + lane];
    gather_row_f(g_g2, w * CAP, len, lane, acc);

    if (lane == 0) g_cnt[w] = 0;   // self-clear for next replay

    float4 bb = ((const float4*)b2)[lane];
    float h[4];
    h[0] = fmaxf(acc.x * s + bb.x, 0.f);
    h[1] = fmaxf(acc.y * s + bb.y, 0.f);
    h[2] = fmaxf(acc.z * s + bb.z, 0.f);
    h[3] = fmaxf(acc.w * s + bb.w, 0.f);

    int c0 = lane * 4;
    float a6[DOUT];
#pragma unroll
    for (int o = 0; o < DOUT; o++) a6[o] = 0.f;
#pragma unroll
    for (int j = 0; j < 4; j++)
#pragma unroll
        for (int o = 0; o < DOUT; o++)
            a6[o] += h[j] * __ldg(&Wfc[(c0 + j) * DOUT + o]);
#pragma unroll
    for (int o = 0; o < DOUT; o++)
        for (int off = 16; off; off >>= 1)
            a6[o] += __shfl_xor_sync(0xffffffffu, a6[o], off);
    if (lane == 0) {
#pragma unroll
        for (int o = 0; o < DOUT; o++) out[(size_t)w * DOUT + o] = a6[o] + bfc[o];
    }
}

// ---------------- launch ----------------------------------------------------
extern "C" void kernel_launch(void* const* d_in, const int* in_sizes, int n_in,
                              void* d_out, int out_size) {
    const float* x   = (const float*)d_in[0];
    const float* W1  = (const float*)d_in[1];
    const float* b1  = (const float*)d_in[2];
    const float* W2  = (const float*)d_in[3];
    const float* b2  = (const float*)d_in[4];
    const float* Wfc = (const float*)d_in[5];
    const float* bfc = (const float*)d_in[6];
    const int*   ei  = (const int*)d_in[7];

    int n = in_sizes[0] / DIN;
    int E = in_sizes[7] / 2;
    const int* src = ei;
    const int* dst = ei + E;
    float* out = (float*)d_out;

    // prep: x->fp16, weights->fp16 transposed, adjacency build
    k_xhalf<<<(n * 32 + 255) / 256, 256>>>(x, n);
    k_round<<<(DIN * H1 + 255) / 256, 256>>>(W1, W2);
    k_fill<<<(E + 255) / 256, 256>>>(src, dst, E);

    // layer 1
    k_gather1<<<(n * 32 + 255) / 256, 256>>>(n);
    {
        dim3 grid((n + 127) / 128, H1 / 128);
        k_gemm_h<1><<<grid, 256>>>(b1, n, H1, DIN);
    }

    // layer 2
    {
        dim3 grid((n + 127) / 128, H2 / 128);
        k_gemm_h<2><<<grid, 256>>>(nullptr, n, H2, H1);
    }
    k_gather2fc<<<(n * 32 + 255) / 256, 256>>>(Wfc, bfc, b2, out, n);
}

// round 11
// speedup vs baseline: 3.5151x; 1.0595x over previous
#include <cuda_runtime.h>
#include <cuda_fp16.h>
#include <cstdint>

#define NMAX 50000
#define EMAX 500000
#define DIN  128   // input feature dim
#define H1   256   // conv1 output dim
#define H2   128   // conv2 output dim
#define DOUT 6
#define CAP  64    // ELL bucket capacity

#define ASTRH 24   // As row stride in halves (16 + 8 pad; 48B rows, 16B-aligned)
#define BSTRH 24   // Bs row stride in halves

// ---------------- scratch (device globals; no allocation allowed) ----------
__device__ __half g_xh  [NMAX * DIN];   // d_s * x_s, fp16 (pre-scaled)
__device__ __half g_accX[NMAX * DIN];   // layer-1 aggregate, fp16 (GEMM1 A)
__device__ __half g_h1  [NMAX * H1];    // relu(conv1), fp16 (GEMM2 A)
__device__ __half g_g2h [NMAX * H2];    // d_i*(h1@W2), fp16
__device__ __half g_W1h [H1 * DIN];     // W1 transposed [n][k], fp16
__device__ __half g_W2h [H2 * H1];      // W2 transposed [n][k], fp16
__device__ int    g_cnt [NMAX];         // in-degree counter (self-clearing)
__device__ int    g_eidx[NMAX * CAP];   // ELL neighbor (src) indices

__device__ __forceinline__ float disq(int cnt) {  // (deg+1)^{-1/2}
    return rsqrtf((float)(cnt + 1));
}

// ---------------- ELL fill (must run before k_xhalf: degrees needed) --------
__global__ void k_fill(const int* __restrict__ src, const int* __restrict__ dst, int E) {
    int i = blockIdx.x * blockDim.x + threadIdx.x;
    if (i < E) {
        int d = dst[i];
        int pos = atomicAdd(&g_cnt[d], 1);
        if (pos < CAP) g_eidx[d * CAP + pos] = src[i];
    }
}

// ---------------- prep: x -> fp16, pre-scaled by d_s ------------------------
__global__ void k_xhalf(const float* __restrict__ x, int n) {
    int i = blockIdx.x * blockDim.x + threadIdx.x;   // float4 index
    if (i >= n * 32) return;
    int row = i >> 5;
    float s = disq(g_cnt[row]);
    float4 v = ((const float4*)x)[i];
    __half2 h0 = __floats2half2_rn(v.x * s, v.y * s);
    __half2 h1 = __floats2half2_rn(v.z * s, v.w * s);
    uint2 o;
    o.x = *reinterpret_cast<const unsigned*>(&h0);
    o.y = *reinterpret_cast<const unsigned*>(&h1);
    ((uint2*)g_xh)[i] = o;
}

// ---------------- prep: weights -> fp16, transposed to [n][k] ---------------
__global__ void k_round(const float* __restrict__ W1, const float* __restrict__ W2) {
    int i = blockIdx.x * blockDim.x + threadIdx.x;
    if (i < DIN * H1) {
        int k = i / H1, nn = i % H1;
        g_W1h[nn * DIN + k] = __float2half_rn(W1[i]);
    }
    if (i < H1 * H2) {
        int k = i / H2, nn = i % H2;
        g_W2h[nn * H1 + k] = __float2half_rn(W2[i]);
    }
}

// ---------------- half gather chunk: C independent neighbor sums ------------
template <int C>
__device__ __forceinline__ void gather_chunk_h(const __half* __restrict__ feat,
                                               int j, int lane, float4& acc) {
    int id[C];
#pragma unroll
    for (int u = 0; u < C; u++) id[u] = g_eidx[j + u];
    uint2 v[C];
#pragma unroll
    for (int u = 0; u < C; u++)
        v[u] = ((const uint2*)feat)[(size_t)id[u] * 32 + lane];
#pragma unroll
    for (int u = 0; u < C; u++) {
        float2 p0 = __half22float2(*reinterpret_cast<__half2*>(&v[u].x));
        float2 p1 = __half22float2(*reinterpret_cast<__half2*>(&v[u].y));
        acc.x += p0.x; acc.y += p0.y; acc.z += p1.x; acc.w += p1.y;
    }
}

__device__ __forceinline__ void gather_row_h(const __half* __restrict__ feat,
                                             int beg, int len, int lane, float4& acc) {
    int j = beg, rem = len;
    while (rem >= 8) { gather_chunk_h<8>(feat, j, lane, acc); j += 8; rem -= 8; }
    if (rem >= 4)    { gather_chunk_h<4>(feat, j, lane, acc); j += 4; rem -= 4; }
    if (rem >= 2)    { gather_chunk_h<2>(feat, j, lane, acc); j += 2; rem -= 2; }
    if (rem)         { gather_chunk_h<1>(feat, j, lane, acc); }
}

// ---------------- layer-1 gather: g_accX[v] = d_v * sum(pre-scaled rows) ----
__global__ void k_gather1(int n) {
    int gtid = blockIdx.x * blockDim.x + threadIdx.x;
    int w = gtid >> 5;
    int lane = threadIdx.x & 31;
    if (w >= n) return;

    int cnt = g_cnt[w];
    int len = min(cnt, CAP);
    float s = disq(cnt);

    // self term: g_xh[w] already = d_v * x_v
    uint2 xv = ((const uint2*)g_xh)[(size_t)w * 32 + lane];
    float2 p0 = __half22float2(*reinterpret_cast<__half2*>(&xv.x));
    float2 p1 = __half22float2(*reinterpret_cast<__half2*>(&xv.y));
    float4 acc = make_float4(p0.x, p0.y, p1.x, p1.y);

    gather_row_h(g_xh, w * CAP, len, lane, acc);

    __half2 o0 = __floats2half2_rn(acc.x * s, acc.y * s);
    __half2 o1 = __floats2half2_rn(acc.z * s, acc.w * s);
    uint2 o;
    o.x = *reinterpret_cast<const unsigned*>(&o0);
    o.y = *reinterpret_cast<const unsigned*>(&o1);
    ((uint2*)g_accX)[(size_t)w * 32 + lane] = o;
}

// ---------------- cp.async helpers ------------------------------------------
__device__ __forceinline__ void cpa16h(__half* dst, const __half* src, int srcbytes) {
    uint32_t d = (uint32_t)__cvta_generic_to_shared(dst);
    asm volatile("cp.async.cg.shared.global [%0], [%1], 16, %2;"
                 :: "r"(d), "l"(src), "r"(srcbytes));
}
__device__ __forceinline__ void cpa_commit() {
    asm volatile("cp.async.commit_group;");
}
template <int N>
__device__ __forceinline__ void cpa_wait() {
    asm volatile("cp.async.wait_group %0;" :: "n"(N));
}

__device__ __forceinline__ void mma_f16(float& c0, float& c1, float& c2, float& c3,
                                        uint32_t a0, uint32_t a1, uint32_t a2, uint32_t a3,
                                        uint32_t b0, uint32_t b1) {
    asm volatile(
        "mma.sync.aligned.m16n8k16.row.col.f32.f16.f16.f32 "
        "{%0,%1,%2,%3},{%4,%5,%6,%7},{%8,%9},{%0,%1,%2,%3};"
        : "+f"(c0), "+f"(c1), "+f"(c2), "+f"(c3)
        : "r"(a0), "r"(a1), "r"(a2), "r"(a3), "r"(b0), "r"(b1));
}

// ---------------- fp16 tensor-core GEMM (3-stage cp.async, 1 barrier/stage) -
// Block 128x128, BK=16, 256 thr = 8 warps (2 x 4), warp tile 64x32.
// A [m][k] fp16 rows; B pre-transposed [n][k] fp16 rows. C = A @ B^T.
// MODE 1 (conv1): A=g_accX, B=g_W1h; C = half(relu(v+b1))  -> g_h1
// MODE 2 (conv2): A=g_h1,   B=g_W2h; C = half(d_row * v)   -> g_g2h
template <int MODE>
__global__ __launch_bounds__(256, 2)
void k_gemm_h(const float* __restrict__ bias, int M, int N, int K) {
    __shared__ __half As[3][128 * ASTRH];
    __shared__ __half Bs[3][128 * BSTRH];

    const __half* A  = (MODE == 1) ? g_accX : g_h1;
    const __half* Bw = (MODE == 1) ? g_W1h  : g_W2h;

    int tid  = threadIdx.x;
    int lane = tid & 31;
    int wid  = tid >> 5;
    int warp_m = wid & 1;   // 0..1 (64 rows)
    int warp_n = wid >> 1;  // 0..3 (32 cols)
    int bm = blockIdx.x * 128;
    int bn = blockIdx.y * 128;
    int lq = lane & 3;      // thread in quad
    int lg = lane >> 2;     // group id

    float c[4][4][4];
#pragma unroll
    for (int mt = 0; mt < 4; mt++)
#pragma unroll
        for (int nt = 0; nt < 4; nt++)
#pragma unroll
            for (int r = 0; r < 4; r++) c[mt][nt][r] = 0.f;

    int nk = K / 16;

    int cm  = tid >> 1;     // row 0..127
    int ck  = tid & 1;      // 16B chunk within 32B row
    int grA = bm + cm;
    const __half* srcA0 = A  + (size_t)min(grA, M - 1) * K + ck * 8;
    const __half* srcB0 = Bw + (size_t)(bn + cm) * K + ck * 8;
    int okA = (grA < M) ? 16 : 0;

    auto load_tile = [&](int kt, int bf) {
        cpa16h(&As[bf][cm * ASTRH + ck * 8], srcA0 + kt * 16, okA);
        cpa16h(&Bs[bf][cm * BSTRH + ck * 8], srcB0 + kt * 16, 16);
    };

    load_tile(0, 0); cpa_commit();
    load_tile(1, 1); cpa_commit();

    for (int kt = 0; kt < nk; kt++) {
        int bf = kt - (kt / 3) * 3;          // kt % 3
        cpa_wait<1>();
        __syncthreads();
        if (kt + 2 < nk) load_tile(kt + 2, (kt + 2) % 3);
        cpa_commit();

        uint32_t a[4][4];
#pragma unroll
        for (int mt = 0; mt < 4; mt++) {
            int mr = warp_m * 64 + mt * 16 + lg;
            const __half* pa = &As[bf][mr * ASTRH + 2 * lq];
            a[mt][0] = *(const uint32_t*)(pa);
            a[mt][1] = *(const uint32_t*)(pa + 8 * ASTRH);
            a[mt][2] = *(const uint32_t*)(pa + 8);
            a[mt][3] = *(const uint32_t*)(pa + 8 * ASTRH + 8);
        }
        uint32_t b[4][2];
#pragma unroll
        for (int nt = 0; nt < 4; nt++) {
            int nc = warp_n * 32 + nt * 8 + lg;
            const __half* pb = &Bs[bf][nc * BSTRH + 2 * lq];
            b[nt][0] = *(const uint32_t*)(pb);
            b[nt][1] = *(const uint32_t*)(pb + 8);
        }
#pragma unroll
        for (int mt = 0; mt < 4; mt++)
#pragma unroll
            for (int nt = 0; nt < 4; nt++)
                mma_f16(c[mt][nt][0], c[mt][nt][1], c[mt][nt][2], c[mt][nt][3],
                        a[mt][0], a[mt][1], a[mt][2], a[mt][3],
                        b[nt][0], b[nt][1]);
    }

    // ---- epilogue ----
#pragma unroll
    for (int mt = 0; mt < 4; mt++) {
        int row0 = bm + warp_m * 64 + mt * 16 + lg;
        int row1 = row0 + 8;
#pragma unroll
        for (int nt = 0; nt < 4; nt++) {
            int col = bn + warp_n * 32 + nt * 8 + lq * 2;
            if (MODE == 1) {
                float2 bb = *(const float2*)(bias + col);
                if (row0 < M) {
                    __half2 v = __floats2half2_rn(fmaxf(c[mt][nt][0] + bb.x, 0.f),
                                                  fmaxf(c[mt][nt][1] + bb.y, 0.f));
                    *(unsigned*)(g_h1 + (size_t)row0 * N + col) =
                        *reinterpret_cast<const unsigned*>(&v);
                }
                if (row1 < M) {
                    __half2 v = __floats2half2_rn(fmaxf(c[mt][nt][2] + bb.x, 0.f),
                                                  fmaxf(c[mt][nt][3] + bb.y, 0.f));
                    *(unsigned*)(g_h1 + (size_t)row1 * N + col) =
                        *reinterpret_cast<const unsigned*>(&v);
                }
            } else {
                if (row0 < M) {
                    float s0 = disq(g_cnt[row0]);
                    __half2 v = __floats2half2_rn(c[mt][nt][0] * s0, c[mt][nt][1] * s0);
                    *(unsigned*)(g_g2h + (size_t)row0 * N + col) =
                        *reinterpret_cast<const unsigned*>(&v);
                }
                if (row1 < M) {
                    float s1 = disq(g_cnt[row1]);
                    __half2 v = __floats2half2_rn(c[mt][nt][2] * s1, c[mt][nt][3] * s1);
                    *(unsigned*)(g_g2h + (size_t)row1 * N + col) =
                        *reinterpret_cast<const unsigned*>(&v);
                }
            }
        }
    }
}

// ---------------- fused layer-2 gather + FC head (clears g_cnt) -------------
__global__ void k_gather2fc(const float* __restrict__ Wfc, const float* __restrict__ bfc,
                            const float* __restrict__ b2, float* __restrict__ out, int n) {
    int gtid = blockIdx.x * blockDim.x + threadIdx.x;
    int w = gtid >> 5;
    int lane = threadIdx.x & 31;
    if (w >= n) return;

    int cnt = g_cnt[w];
    int len = min(cnt, CAP);
    float s = disq(cnt);

    uint2 gv = ((const uint2*)g_g2h)[(size_t)w * 32 + lane];
    float2 p0 = __half22float2(*reinterpret_cast<__half2*>(&gv.x));
    float2 p1 = __half22float2(*reinterpret_cast<__half2*>(&gv.y));
    float4 acc = make_float4(p0.x, p0.y, p1.x, p1.y);

    gather_row_h(g_g2h, w * CAP, len, lane, acc);

    if (lane == 0) g_cnt[w] = 0;   // self-clear for next replay

    float4 bb = ((const float4*)b2)[lane];
    float h[4];
    h[0] = fmaxf(acc.x * s + bb.x, 0.f);
    h[1] = fmaxf(acc.y * s + bb.y, 0.f);
    h[2] = fmaxf(acc.z * s + bb.z, 0.f);
    h[3] = fmaxf(acc.w * s + bb.w, 0.f);

    int c0 = lane * 4;
    float a6[DOUT];
#pragma unroll
    for (int o = 0; o < DOUT; o++) a6[o] = 0.f;
#pragma unroll
    for (int j = 0; j < 4; j++)
#pragma unroll
        for (int o = 0; o < DOUT; o++)
            a6[o] += h[j] * __ldg(&Wfc[(c0 + j) * DOUT + o]);
#pragma unroll
    for (int o = 0; o < DOUT; o++)
        for (int off = 16; off; off >>= 1)
            a6[o] += __shfl_xor_sync(0xffffffffu, a6[o], off);
    if (lane == 0) {
#pragma unroll
        for (int o = 0; o < DOUT; o++) out[(size_t)w * DOUT + o] = a6[o] + bfc[o];
    }
}

// ---------------- launch ----------------------------------------------------
extern "C" void kernel_launch(void* const* d_in, const int* in_sizes, int n_in,
                              void* d_out, int out_size) {
    const float* x   = (const float*)d_in[0];
    const float* W1  = (const float*)d_in[1];
    const float* b1  = (const float*)d_in[2];
    const float* W2  = (const float*)d_in[3];
    const float* b2  = (const float*)d_in[4];
    const float* Wfc = (const float*)d_in[5];
    const float* bfc = (const float*)d_in[6];
    const int*   ei  = (const int*)d_in[7];

    int n = in_sizes[0] / DIN;
    int E = in_sizes[7] / 2;
    const int* src = ei;
    const int* dst = ei + E;
    float* out = (float*)d_out;

    // adjacency + degrees first (k_xhalf needs degrees for pre-scaling)
    k_fill<<<(E + 255) / 256, 256>>>(src, dst, E);
    k_round<<<(DIN * H1 + 255) / 256, 256>>>(W1, W2);   // independent of fill
    k_xhalf<<<(n * 32 + 255) / 256, 256>>>(x, n);

    // layer 1
    k_gather1<<<(n * 32 + 255) / 256, 256>>>(n);
    {
        dim3 grid((n + 127) / 128, H1 / 128);
        k_gemm_h<1><<<grid, 256>>>(b1, n, H1, DIN);
    }

    // layer 2
    {
        dim3 grid((n + 127) / 128, H2 / 128);
        k_gemm_h<2><<<grid, 256>>>(nullptr, n, H2, H1);
    }
    k_gather2fc<<<(n * 32 + 255) / 256, 256>>>(Wfc, bfc, b2, out, n);
}

// round 12
// speedup vs baseline: 3.6792x; 1.0467x over previous
#include <cuda_runtime.h>
#include <cuda_fp16.h>
#include <cstdint>

#define NMAX 50000
#define EMAX 500000
#define DIN  128   // input feature dim
#define H1   256   // conv1 output dim
#define H2   128   // conv2 output dim
#define DOUT 6
#define CAP  64    // ELL bucket capacity

#define ASTRH 24   // As row stride in halves (48B rows; ldmatrix conflict-free)
#define BSTRH 24   // Bs row stride in halves
#define STAGE_B (128 * ASTRH * 2)   // 6144 bytes per stage

// ---------------- scratch (device globals; no allocation allowed) ----------
__device__ __half g_xh  [NMAX * DIN];   // d_s * x_s, fp16 (pre-scaled)
__device__ __half g_accX[NMAX * DIN];   // layer-1 aggregate, fp16 (GEMM1 A)
__device__ __half g_h1  [NMAX * H1];    // relu(conv1), fp16 (GEMM2 A)
__device__ __half g_g2h [NMAX * H2];    // d_i*(h1@W2), fp16
__device__ __half g_W1h [H1 * DIN];     // W1 transposed [n][k], fp16
__device__ __half g_W2h [H2 * H1];      // W2 transposed [n][k], fp16
__device__ int    g_cnt [NMAX];         // in-degree counter (self-clearing)
__device__ int    g_eidx[NMAX * CAP];   // ELL neighbor (src) indices

__device__ __forceinline__ float disq(int cnt) {  // (deg+1)^{-1/2}
    return rsqrtf((float)(cnt + 1));
}

// ---------------- packed f32x2 add (exact, element-wise) --------------------
__device__ __forceinline__ void fadd2(float2& a, float2 b) {
    asm("add.rn.f32x2 %0, %0, %1;"
        : "+l"(*reinterpret_cast<unsigned long long*>(&a))
        : "l"(*reinterpret_cast<const unsigned long long*>(&b)));
}

// ---------------- ELL fill + weight convert (merged, disjoint blocks) -------
__global__ void k_fillround(const int* __restrict__ src, const int* __restrict__ dst,
                            int E, int fillBlocks,
                            const float* __restrict__ W1, const float* __restrict__ W2) {
    if ((int)blockIdx.x < fillBlocks) {
        int i = blockIdx.x * blockDim.x + threadIdx.x;
        if (i < E) {
            int d = dst[i];
            int pos = atomicAdd(&g_cnt[d], 1);
            if (pos < CAP) g_eidx[d * CAP + pos] = src[i];
        }
    } else {
        int i = (blockIdx.x - fillBlocks) * blockDim.x + threadIdx.x;
        if (i < DIN * H1) {
            int k = i / H1, nn = i % H1;
            g_W1h[nn * DIN + k] = __float2half_rn(W1[i]);
        }
        if (i < H1 * H2) {
            int k = i / H2, nn = i % H2;
            g_W2h[nn * H1 + k] = __float2half_rn(W2[i]);
        }
    }
}

// ---------------- prep: x -> fp16, pre-scaled by d_s ------------------------
__global__ void k_xhalf(const float* __restrict__ x, int n) {
    int i = blockIdx.x * blockDim.x + threadIdx.x;   // float4 index
    if (i >= n * 32) return;
    int row = i >> 5;
    float s = disq(g_cnt[row]);
    float4 v = ((const float4*)x)[i];
    __half2 h0 = __floats2half2_rn(v.x * s, v.y * s);
    __half2 h1 = __floats2half2_rn(v.z * s, v.w * s);
    uint2 o;
    o.x = *reinterpret_cast<const unsigned*>(&h0);
    o.y = *reinterpret_cast<const unsigned*>(&h1);
    ((uint2*)g_xh)[i] = o;
}

// ---------------- half gather chunk: C independent neighbor sums ------------
template <int C>
__device__ __forceinline__ void gather_chunk_h(const __half* __restrict__ feat,
                                               int j, int lane,
                                               float2& acc01, float2& acc23) {
    int id[C];
#pragma unroll
    for (int u = 0; u < C; u++) id[u] = g_eidx[j + u];
    uint2 v[C];
#pragma unroll
    for (int u = 0; u < C; u++)
        v[u] = ((const uint2*)feat)[(size_t)id[u] * 32 + lane];
#pragma unroll
    for (int u = 0; u < C; u++) {
        fadd2(acc01, __half22float2(*reinterpret_cast<__half2*>(&v[u].x)));
        fadd2(acc23, __half22float2(*reinterpret_cast<__half2*>(&v[u].y)));
    }
}

__device__ __forceinline__ void gather_row_h(const __half* __restrict__ feat,
                                             int beg, int len, int lane,
                                             float2& acc01, float2& acc23) {
    int j = beg, rem = len;
    while (rem >= 8) { gather_chunk_h<8>(feat, j, lane, acc01, acc23); j += 8; rem -= 8; }
    if (rem >= 4)    { gather_chunk_h<4>(feat, j, lane, acc01, acc23); j += 4; rem -= 4; }
    if (rem >= 2)    { gather_chunk_h<2>(feat, j, lane, acc01, acc23); j += 2; rem -= 2; }
    if (rem)         { gather_chunk_h<1>(feat, j, lane, acc01, acc23); }
}

// ---------------- layer-1 gather: g_accX[v] = d_v * sum(pre-scaled rows) ----
__global__ void k_gather1(int n) {
    int gtid = blockIdx.x * blockDim.x + threadIdx.x;
    int w = gtid >> 5;
    int lane = threadIdx.x & 31;
    if (w >= n) return;

    int cnt = g_cnt[w];
    int len = min(cnt, CAP);
    float s = disq(cnt);

    uint2 xv = ((const uint2*)g_xh)[(size_t)w * 32 + lane];
    float2 acc01 = __half22float2(*reinterpret_cast<__half2*>(&xv.x));
    float2 acc23 = __half22float2(*reinterpret_cast<__half2*>(&xv.y));

    gather_row_h(g_xh, w * CAP, len, lane, acc01, acc23);

    __half2 o0 = __floats2half2_rn(acc01.x * s, acc01.y * s);
    __half2 o1 = __floats2half2_rn(acc23.x * s, acc23.y * s);
    uint2 o;
    o.x = *reinterpret_cast<const unsigned*>(&o0);
    o.y = *reinterpret_cast<const unsigned*>(&o1);
    ((uint2*)g_accX)[(size_t)w * 32 + lane] = o;
}

// ---------------- cp.async / ldmatrix / mma helpers -------------------------
__device__ __forceinline__ void cpa16h(__half* dst, const __half* src, int srcbytes) {
    uint32_t d = (uint32_t)__cvta_generic_to_shared(dst);
    asm volatile("cp.async.cg.shared.global [%0], [%1], 16, %2;"
                 :: "r"(d), "l"(src), "r"(srcbytes));
}
__device__ __forceinline__ void cpa_commit() {
    asm volatile("cp.async.commit_group;");
}
template <int N>
__device__ __forceinline__ void cpa_wait() {
    asm volatile("cp.async.wait_group %0;" :: "n"(N));
}

__device__ __forceinline__ void ldsm4(uint32_t& r0, uint32_t& r1, uint32_t& r2,
                                      uint32_t& r3, uint32_t addr) {
    asm volatile("ldmatrix.sync.aligned.m8n8.x4.shared.b16 {%0,%1,%2,%3}, [%4];"
                 : "=r"(r0), "=r"(r1), "=r"(r2), "=r"(r3) : "r"(addr));
}

__device__ __forceinline__ void mma_f16(float& c0, float& c1, float& c2, float& c3,
                                        uint32_t a0, uint32_t a1, uint32_t a2, uint32_t a3,
                                        uint32_t b0, uint32_t b1) {
    asm volatile(
        "mma.sync.aligned.m16n8k16.row.col.f32.f16.f16.f32 "
        "{%0,%1,%2,%3},{%4,%5,%6,%7},{%8,%9},{%0,%1,%2,%3};"
        : "+f"(c0), "+f"(c1), "+f"(c2), "+f"(c3)
        : "r"(a0), "r"(a1), "r"(a2), "r"(a3), "r"(b0), "r"(b1));
}

// ---------------- fp16 tensor-core GEMM (3-stage cp.async + ldmatrix) -------
// Block 128x128, BK=16, 256 thr = 8 warps (2 x 4), warp tile 64x32.
// A [m][k] fp16 rows; B pre-transposed [n][k] fp16 rows. C = A @ B^T.
// MODE 1 (conv1): A=g_accX, B=g_W1h; C = half(relu(v+b1))  -> g_h1
// MODE 2 (conv2): A=g_h1,   B=g_W2h; C = half(d_row * v)   -> g_g2h
template <int MODE>
__global__ __launch_bounds__(256, 2)
void k_gemm_h(const float* __restrict__ bias, int M, int N, int K) {
    __shared__ __half As[3][128 * ASTRH];
    __shared__ __half Bs[3][128 * BSTRH];

    const __half* A  = (MODE == 1) ? g_accX : g_h1;
    const __half* Bw = (MODE == 1) ? g_W1h  : g_W2h;

    int tid  = threadIdx.x;
    int lane = tid & 31;
    int wid  = tid >> 5;
    int warp_m = wid & 1;   // 0..1 (64 rows)
    int warp_n = wid >> 1;  // 0..3 (32 cols)
    int bm = blockIdx.x * 128;
    int bn = blockIdx.y * 128;
    int lq = lane & 3;
    int lg = lane >> 2;

    float c[4][4][4];
#pragma unroll
    for (int mt = 0; mt < 4; mt++)
#pragma unroll
        for (int nt = 0; nt < 4; nt++)
#pragma unroll
            for (int r = 0; r < 4; r++) c[mt][nt][r] = 0.f;

    int nk = K / 16;

    // cp.async staging addressing
    int cm  = tid >> 1;     // row 0..127
    int ck  = tid & 1;      // 16B chunk within 32B row
    int grA = bm + cm;
    const __half* srcA0 = A  + (size_t)min(grA, M - 1) * K + ck * 8;
    const __half* srcB0 = Bw + (size_t)(bn + cm) * K + ck * 8;
    int okA = (grA < M) ? 16 : 0;

    auto load_tile = [&](int kt, int bf) {
        cpa16h(&As[bf][cm * ASTRH + ck * 8], srcA0 + kt * 16, okA);
        cpa16h(&Bs[bf][cm * BSTRH + ck * 8], srcB0 + kt * 16, 16);
    };

    // ldmatrix per-lane base offsets (row = lane&15, col-half = (lane>>4)*8)
    uint32_t asb = (uint32_t)__cvta_generic_to_shared(&As[0][0]);
    uint32_t bsb = (uint32_t)__cvta_generic_to_shared(&Bs[0][0]);
    uint32_t lmOff = ((lane & 15) * ASTRH + (lane >> 4) * 8) * 2;

    load_tile(0, 0); cpa_commit();
    load_tile(1, 1); cpa_commit();

    for (int kt = 0; kt < nk; kt++) {
        int bf = kt - (kt / 3) * 3;          // kt % 3
        cpa_wait<1>();
        __syncthreads();
        if (kt + 2 < nk) load_tile(kt + 2, (kt + 2) % 3);
        cpa_commit();

        uint32_t a[4][4];
#pragma unroll
        for (int mt = 0; mt < 4; mt++) {
            uint32_t addr = asb + bf * STAGE_B + (warp_m * 64 + mt * 16) * (ASTRH * 2) + lmOff;
            ldsm4(a[mt][0], a[mt][1], a[mt][2], a[mt][3], addr);
        }
        uint32_t b[4][2];
#pragma unroll
        for (int ntp = 0; ntp < 2; ntp++) {
            uint32_t r0, r1, r2, r3;
            uint32_t addr = bsb + bf * STAGE_B + (warp_n * 32 + ntp * 16) * (BSTRH * 2) + lmOff;
            ldsm4(r0, r1, r2, r3, addr);
            b[ntp * 2 + 0][0] = r0;   // rows n..n+7,  k0-7
            b[ntp * 2 + 1][0] = r1;   // rows n+8..15, k0-7
            b[ntp * 2 + 0][1] = r2;   // rows n..n+7,  k8-15
            b[ntp * 2 + 1][1] = r3;   // rows n+8..15, k8-15
        }
#pragma unroll
        for (int mt = 0; mt < 4; mt++)
#pragma unroll
            for (int nt = 0; nt < 4; nt++)
                mma_f16(c[mt][nt][0], c[mt][nt][1], c[mt][nt][2], c[mt][nt][3],
                        a[mt][0], a[mt][1], a[mt][2], a[mt][3],
                        b[nt][0], b[nt][1]);
    }

    // ---- epilogue ----
#pragma unroll
    for (int mt = 0; mt < 4; mt++) {
        int row0 = bm + warp_m * 64 + mt * 16 + lg;
        int row1 = row0 + 8;
#pragma unroll
        for (int nt = 0; nt < 4; nt++) {
            int col = bn + warp_n * 32 + nt * 8 + lq * 2;
            if (MODE == 1) {
                float2 bb = *(const float2*)(bias + col);
                if (row0 < M) {
                    __half2 v = __floats2half2_rn(fmaxf(c[mt][nt][0] + bb.x, 0.f),
                                                  fmaxf(c[mt][nt][1] + bb.y, 0.f));
                    *(unsigned*)(g_h1 + (size_t)row0 * N + col) =
                        *reinterpret_cast<const unsigned*>(&v);
                }
                if (row1 < M) {
                    __half2 v = __floats2half2_rn(fmaxf(c[mt][nt][2] + bb.x, 0.f),
                                                  fmaxf(c[mt][nt][3] + bb.y, 0.f));
                    *(unsigned*)(g_h1 + (size_t)row1 * N + col) =
                        *reinterpret_cast<const unsigned*>(&v);
                }
            } else {
                if (row0 < M) {
                    float s0 = disq(g_cnt[row0]);
                    __half2 v = __floats2half2_rn(c[mt][nt][0] * s0, c[mt][nt][1] * s0);
                    *(unsigned*)(g_g2h + (size_t)row0 * N + col) =
                        *reinterpret_cast<const unsigned*>(&v);
                }
                if (row1 < M) {
                    float s1 = disq(g_cnt[row1]);
                    __half2 v = __floats2half2_rn(c[mt][nt][2] * s1, c[mt][nt][3] * s1);
                    *(unsigned*)(g_g2h + (size_t)row1 * N + col) =
                        *reinterpret_cast<const unsigned*>(&v);
                }
            }
        }
    }
}

// ---------------- fused layer-2 gather + FC head (clears g_cnt) -------------
__global__ void k_gather2fc(const float* __restrict__ Wfc, const float* __restrict__ bfc,
                            const float* __restrict__ b2, float* __restrict__ out, int n) {
    int gtid = blockIdx.x * blockDim.x + threadIdx.x;
    int w = gtid >> 5;
    int lane = threadIdx.x & 31;
    if (w >= n) return;

    int cnt = g_cnt[w];
    int len = min(cnt, CAP);
    float s = disq(cnt);

    uint2 gv = ((const uint2*)g_g2h)[(size_t)w * 32 + lane];
    float2 acc01 = __half22float2(*reinterpret_cast<__half2*>(&gv.x));
    float2 acc23 = __half22float2(*reinterpret_cast<__half2*>(&gv.y));

    gather_row_h(g_g2h, w * CAP, len, lane, acc01, acc23);

    if (lane == 0) g_cnt[w] = 0;   // self-clear for next replay

    float4 bb = ((const float4*)b2)[lane];
    float h[4];
    h[0] = fmaxf(acc01.x * s + bb.x, 0.f);
    h[1] = fmaxf(acc01.y * s + bb.y, 0.f);
    h[2] = fmaxf(acc23.x * s + bb.z, 0.f);
    h[3] = fmaxf(acc23.y * s + bb.w, 0.f);

    int c0 = lane * 4;
    float a6[DOUT];
#pragma unroll
    for (int o = 0; o < DOUT; o++) a6[o] = 0.f;
#pragma unroll
    for (int j = 0; j < 4; j++)
#pragma unroll
        for (int o = 0; o < DOUT; o++)
            a6[o] += h[j] * __ldg(&Wfc[(c0 + j) * DOUT + o]);
#pragma unroll
    for (int o = 0; o < DOUT; o++)
        for (int off = 16; off; off >>= 1)
            a6[o] += __shfl_xor_sync(0xffffffffu, a6[o], off);
    if (lane == 0) {
#pragma unroll
        for (int o = 0; o < DOUT; o++) out[(size_t)w * DOUT + o] = a6[o] + bfc[o];
    }
}

// ---------------- launch ----------------------------------------------------
extern "C" void kernel_launch(void* const* d_in, const int* in_sizes, int n_in,
                              void* d_out, int out_size) {
    const float* x   = (const float*)d_in[0];
    const float* W1  = (const float*)d_in[1];
    const float* b1  = (const float*)d_in[2];
    const float* W2  = (const float*)d_in[3];
    const float* b2  = (const float*)d_in[4];
    const float* Wfc = (const float*)d_in[5];
    const float* bfc = (const float*)d_in[6];
    const int*   ei  = (const int*)d_in[7];

    int n = in_sizes[0] / DIN;
    int E = in_sizes[7] / 2;
    const int* src = ei;
    const int* dst = ei + E;
    float* out = (float*)d_out;

    // adjacency + degrees + weight convert (merged)
    int fillBlocks = (E + 255) / 256;
    int roundBlocks = (DIN * H1 + 255) / 256;   // covers H1*H2 too (equal size)
    k_fillround<<<fillBlocks + roundBlocks, 256>>>(src, dst, E, fillBlocks, W1, W2);
    k_xhalf<<<(n * 32 + 255) / 256, 256>>>(x, n);

    // layer 1
    k_gather1<<<(n * 32 + 255) / 256, 256>>>(n);
    {
        dim3 grid((n + 127) / 128, H1 / 128);
        k_gemm_h<1><<<grid, 256>>>(b1, n, H1, DIN);
    }

    // layer 2
    {
        dim3 grid((n + 127) / 128, H2 / 128);
        k_gemm_h<2><<<grid, 256>>>(nullptr, n, H2, H1);
    }
    k_gather2fc<<<(n * 32 + 255) / 256, 256>>>(Wfc, bfc, b2, out, n);
}